// round 13
// baseline (speedup 1.0000x reference)
#include <cuda_runtime.h>
#include <cuda_bf16.h>
#include <cstdint>

#define BATCH 4
#define NPTS  2048
#define KNN   16
#define BN_ALL (BATCH*NPTS)      // 8192
#define M_COLS (BN_ALL*3)        // 24576

// weight buffer offsets (elements)
#define WOF_L2 0
#define WOF_L3 2048
#define WOF_L4 10240
#define WOF_C  43008
#define WOF_I1 73728
#define WOF_I2 106496
#define W_TOT  172032

// ------------------------- scratch (device globals; no mallocs) -------------
static __device__ __align__(16) float g_X0[BN_ALL*3];
static __device__ __align__(16) float4 g_pts4[BN_ALL];   // (x,y,z,|x|^2)
static __device__ int   g_idx[BN_ALL*KNN];
static __device__ __align__(16) float g_knnd[BN_ALL*64];
static __device__ __align__(16) int   g_knni[BN_ALL*64];
static __device__ __align__(16) float g_xcat240[BN_ALL*3*240];
static __device__ __align__(16) float g_xcat256[BN_ALL*3*256];
static __device__ __align__(16) float g_t128 [BN_ALL*3*128];
static __device__ __align__(16) float g_Y    [BN_ALL*1536];   // reused per layer
static __device__ float g_dc  [M_COLS];
static __device__ float g_xm  [BATCH*3*128];
static __device__ float g_xmp [BATCH*3*32*128];
static __device__ float g_bias[BATCH*3*512];
static __device__ __align__(16) __nv_bfloat16 g_Wh[W_TOT];
static __device__ __align__(16) __nv_bfloat16 g_Wl[W_TOT];

// ------------------------- helpers ------------------------------------------
__device__ __forceinline__ void lna3(float p0,float p1,float p2,
                                     float q0,float q1,float q2,
                                     float&o0,float&o1,float&o2)
{
    float dot = p0*q0 + p1*q1 + p2*q2;
    float dsq = q0*q0 + q1*q1 + q2*q2;
    float s = (dot < 0.f) ? 0.8f*dot/(dsq + 1e-6f) : 0.f;
    o0 = p0 - s*q0; o1 = p1 - s*q1; o2 = p2 - s*q2;
}

__device__ __forceinline__ uint32_t cvt2bf(float x, float y, bool lo)
{
    __nv_bfloat16 hx = __float2bfloat16(x), hy = __float2bfloat16(y);
    if (lo){
        hx = __float2bfloat16(x - __bfloat162float(hx));
        hy = __float2bfloat16(y - __bfloat162float(hy));
    }
    __nv_bfloat162 p; p.x = hx; p.y = hy;
    return *(uint32_t*)&p;
}

// ------------------------- prep / KNN ----------------------------------------
__global__ void k_prep(const float* __restrict__ x)
{
    int i = blockIdx.x*blockDim.x + threadIdx.x;
    if (i >= BN_ALL) return;
    int b = i / NPTS, n = i - b*NPTS;
    float vx = x[(b*3+0)*NPTS + n];
    float vy = x[(b*3+1)*NPTS + n];
    float vz = x[(b*3+2)*NPTS + n];
    g_X0[i*3+0]=vx; g_X0[i*3+1]=vy; g_X0[i*3+2]=vz;
    float sq = fmaf(vz,vz, fmaf(vy,vy, vx*vx));
    float4 p; p.x=vx; p.y=vy; p.z=vz; p.w=sq;
    g_pts4[i] = p;
}

__global__ void k_knn_part()
{
    int t = blockIdx.x*blockDim.x + threadIdx.x;
    if (t >= BN_ALL*4) return;
    int bn    = t & (BN_ALL-1);
    int chunk = t >> 13;
    int b = bn / NPTS;
    float4 pv = g_pts4[bn];
    float px = pv.x, py = pv.y, pz = pv.z, sn = pv.w;
    const float4* Pb = g_pts4 + b*NPTS;

    float bd[KNN]; int bi[KNN];
    #pragma unroll
    for (int i = 0; i < KNN; i++){ bd[i] = 3.4e38f; bi[i] = 0; }
    int m0 = chunk*512;
    #pragma unroll 4
    for (int mm = 0; mm < 512; mm++){
        int m = m0 + mm;
        float4 c = Pb[m];
        float dot = fmaf(pz,c.z, fmaf(py,c.y, px*c.x));
        float d2  = (sn + c.w) - 2.f*dot;
        if (d2 < bd[KNN-1]){
            int p = KNN-1;
            while (p > 0 && bd[p-1] > d2){ bd[p]=bd[p-1]; bi[p]=bi[p-1]; p--; }
            bd[p] = d2; bi[p] = m;
        }
    }
    float* od = g_knnd + bn*64 + chunk*16;
    int*   oi = g_knni + bn*64 + chunk*16;
    #pragma unroll
    for (int i = 0; i < 4; i++){
        float4 vd = { bd[i*4], bd[i*4+1], bd[i*4+2], bd[i*4+3] };
        int4   vi = { bi[i*4], bi[i*4+1], bi[i*4+2], bi[i*4+3] };
        *(float4*)(od + i*4) = vd;
        *(int4*)(oi + i*4)   = vi;
    }
}

// r9-proven merge: per-run early exit over [bn][64] layout.
// blockDim 32 -> 256 blocks -> all SMs participate (latency-bound kernel).
__global__ void k_knn_merge()
{
    int bn = blockIdx.x*blockDim.x + threadIdx.x;
    if (bn >= BN_ALL) return;
    float md[KNN]; int mi[KNN];
    #pragma unroll
    for (int i = 0; i < KNN; i++){ md[i] = 3.4e38f; mi[i] = 0; }
    for (int ch = 0; ch < 4; ch++){
        const float* cd = g_knnd + bn*64 + ch*16;
        const int*   ci = g_knni + bn*64 + ch*16;
        for (int k = 0; k < KNN; k++){
            float d2 = cd[k];
            if (d2 >= md[KNN-1]) break;      // rest of this ascending run fails
            int ix = ci[k];
            int p = KNN-1;
            while (p > 0 && md[p-1] > d2){ md[p]=md[p-1]; mi[p]=mi[p-1]; p--; }
            md[p] = d2; mi[p] = ix;
        }
    }
    #pragma unroll
    for (int i = 0; i < KNN; i++) g_idx[bn*KNN + i] = mi[i];
}

// ------------------------- layer 1 direct Y build (C=1, O=16), vec4 ---------
__global__ void k_layer1(const float* __restrict__ w1f, const float* __restrict__ w1d)
{
    int t = blockIdx.x*blockDim.x + threadIdx.x;
    if (t >= BN_ALL*48) return;
    int bn = t / 48, r = t - bn*48;
    int pl = r >> 2, o4 = (r & 3)*4;
    int g = pl / 3, d = pl - g*3;
    float xv = g_X0[bn*3 + d];
    const float* W = (g < 2) ? w1f : w1d;
    float4 wa = *(const float4*)&W[o4*2];
    float4 wb = *(const float4*)&W[o4*2 + 4];
    float4 out;
    if ((g & 1) == 0){
        out.x = wa.x*xv; out.y = wa.z*xv; out.z = wb.x*xv; out.w = wb.z*xv;
    } else {
        out.x = (wa.y-wa.x)*xv; out.y = (wa.w-wa.z)*xv;
        out.z = (wb.y-wb.x)*xv; out.w = (wb.w-wb.z)*xv;
    }
    *(float4*)&g_Y[(size_t)bn*192 + pl*16 + o4] = out;
}

// ------------------------- ONE combined weight-combine kernel ---------------
__device__ __forceinline__ void split_store(size_t idx, float v)
{
    __nv_bfloat16 h = __float2bfloat16(v);
    g_Wh[idx] = h;
    g_Wl[idx] = __float2bfloat16(v - __bfloat162float(h));
}

__device__ __forceinline__ float graph_w(const float* Wf, const float* Wd,
                                         int C, int O, int local)
{
    int r = local / C, c = local - r*C;
    int g = r / O, o = r - g*O;
    if (g == 0) return Wf[o*2*C + c];
    if (g == 1) return Wf[o*2*C + C + c] - Wf[o*2*C + c];
    if (g == 2) return Wd[o*2*C + c];
    return Wd[o*2*C + C + c] - Wd[o*2*C + c];
}

__global__ void k_wcomb_all(const float* __restrict__ w2f, const float* __restrict__ w2d,
                            const float* __restrict__ w3f, const float* __restrict__ w3d,
                            const float* __restrict__ w4f, const float* __restrict__ w4d,
                            const float* __restrict__ wcf,
                            const float* __restrict__ wi1f, const float* __restrict__ wi1d,
                            const float* __restrict__ wi2f, const float* __restrict__ wi2d)
{
    int t = blockIdx.x*blockDim.x + threadIdx.x;
    if (t >= W_TOT) return;
    float v;
    if (t < WOF_L3)      v = graph_w(w2f, w2d, 16, 32,  t - WOF_L2);
    else if (t < WOF_L4) v = graph_w(w3f, w3d, 32, 64,  t - WOF_L3);
    else if (t < WOF_C)  v = graph_w(w4f, w4d, 64, 128, t - WOF_L4);
    else if (t < WOF_I1) v = wcf[t - WOF_C];
    else if (t < WOF_I2){
        int l = t - WOF_I1, r = l >> 7, c = l & 127;
        v = (r < 128) ? wi1f[r*256 + c] : wi1d[(r-128)*256 + c];
    } else {
        int l = t - WOF_I2, r = l >> 7, c = l & 127;
        v = (r < 256) ? wi2f[r*128 + c] : wi2d[(r-256)*128 + c];
    }
    split_store(t, v);
}

// ------------------------- warp-MMA GEMM (double-buffered) ------------------
#define SWZ(off) ((off) ^ (((off)>>3)&0x30))

__device__ __forceinline__ void ldsm_x4(uint32_t* a, uint32_t addr)
{
    asm volatile("ldmatrix.sync.aligned.m8n8.x4.shared.b16 {%0,%1,%2,%3}, [%4];"
        : "=r"(a[0]),"=r"(a[1]),"=r"(a[2]),"=r"(a[3]) : "r"(addr));
}
__device__ __forceinline__ void ldsm_x2(uint32_t* b, uint32_t addr)
{
    asm volatile("ldmatrix.sync.aligned.m8n8.x2.shared.b16 {%0,%1}, [%2];"
        : "=r"(b[0]),"=r"(b[1]) : "r"(addr));
}
__device__ __forceinline__ void mma16816(float* d, const uint32_t* a, const uint32_t* b)
{
    asm volatile("mma.sync.aligned.m16n8k16.row.col.f32.bf16.bf16.f32 "
        "{%0,%1,%2,%3}, {%4,%5,%6,%7}, {%8,%9}, {%0,%1,%2,%3};"
        : "+f"(d[0]),"+f"(d[1]),"+f"(d[2]),"+f"(d[3])
        : "r"(a[0]),"r"(a[1]),"r"(a[2]),"r"(a[3]),"r"(b[0]),"r"(b[1]));
}

__global__ void __launch_bounds__(256) k_hgemm(int xsel, int useBias, int wofs,
                                               int R, int C, int CS, int co,
                                               int G, int O)
{
    __shared__ __align__(16) char sA[2][128*64];
    __shared__ __align__(16) char sB[2][128*64];
    const float* __restrict__ X = (xsel==0) ? g_xcat240 : (xsel==1) ? g_xcat256 : g_t128;

    int tid  = threadIdx.x, lane = tid & 31, warp = tid >> 5;
    int m0   = blockIdx.x*128, r0 = blockIdx.y*128;
    int nch  = (C + 31) >> 5;
    int EXT  = 3*nch;
    int wr   = (warp >> 2)*64;
    int wm   = (warp & 3)*32;

    int srow = tid >> 1, shalf = tid & 1;

    float acc[4][4][4];
    #pragma unroll
    for (int i=0;i<4;i++)
        #pragma unroll
        for (int j=0;j<4;j++)
            #pragma unroll
            for (int k=0;k<4;k++) acc[i][j][k]=0.f;

    uint4 aS0, aS1, bS0, bS1;

    auto stage = [&](int e){
        int term = e / nch, cblk = e - term*nch;
        bool valid = (cblk*32 + shalf*16) < C;
        const uint4 z = {0,0,0,0};
        if (valid){
            const __nv_bfloat16* Wsrc = (term == 1) ? g_Wl : g_Wh;
            const uint4* p = (const uint4*)&Wsrc[wofs + (size_t)(r0+srow)*C + cblk*32 + shalf*16];
            aS0 = p[0]; aS1 = p[1];
            bool lo = (term == 2);
            const float4* q = (const float4*)&X[(size_t)(m0+srow)*CS + co + cblk*32 + shalf*16];
            float4 f0=q[0], f1=q[1], f2=q[2], f3=q[3];
            bS0.x = cvt2bf(f0.x,f0.y,lo); bS0.y = cvt2bf(f0.z,f0.w,lo);
            bS0.z = cvt2bf(f1.x,f1.y,lo); bS0.w = cvt2bf(f1.z,f1.w,lo);
            bS1.x = cvt2bf(f2.x,f2.y,lo); bS1.y = cvt2bf(f2.z,f2.w,lo);
            bS1.z = cvt2bf(f3.x,f3.y,lo); bS1.w = cvt2bf(f3.z,f3.w,lo);
        } else { aS0=aS1=bS0=bS1=z; }
    };
    auto commit = [&](int buf){
        uint32_t o0 = SWZ((uint32_t)(srow*64 + (shalf*2  )*16));
        uint32_t o1 = SWZ((uint32_t)(srow*64 + (shalf*2+1)*16));
        *(uint4*)(sA[buf]+o0) = aS0;  *(uint4*)(sA[buf]+o1) = aS1;
        *(uint4*)(sB[buf]+o0) = bS0;  *(uint4*)(sB[buf]+o1) = bS1;
    };

    stage(0); commit(0); __syncthreads();

    for (int e = 0; e < EXT; e++){
        if (e+1 < EXT) stage(e+1);
        int buf = e & 1;
        uint32_t baseA = (uint32_t)__cvta_generic_to_shared(sA[buf]);
        uint32_t baseB = (uint32_t)__cvta_generic_to_shared(sB[buf]);
        #pragma unroll
        for (int ks = 0; ks < 32; ks += 16){
            uint32_t a[4][4], b[4][2];
            #pragma unroll
            for (int i = 0; i < 4; i++){
                uint32_t off = (uint32_t)((wr + i*16 + (lane & 15))*64 + ks*2 + (lane >> 4)*16);
                ldsm_x4(a[i], baseA + SWZ(off));
            }
            #pragma unroll
            for (int j = 0; j < 4; j++){
                uint32_t off = (uint32_t)((wm + j*8 + (lane & 7))*64 + ks*2 + ((lane >> 3) & 1)*16);
                ldsm_x2(b[j], baseB + SWZ(off));
            }
            #pragma unroll
            for (int i = 0; i < 4; i++)
                #pragma unroll
                for (int j = 0; j < 4; j++)
                    mma16816(acc[i][j], a[i], b[j]);
        }
        if (e+1 < EXT) commit((e+1) & 1);
        __syncthreads();
    }

    #pragma unroll
    for (int i = 0; i < 4; i++){
        #pragma unroll
        for (int rh = 0; rh < 2; rh++){
            int r = r0 + wr + i*16 + (lane >> 2) + rh*8;
            int g = r / O, o = r - g*O;
            #pragma unroll
            for (int j = 0; j < 4; j++){
                #pragma unroll
                for (int c = 0; c < 2; c++){
                    int m  = m0 + wm + j*8 + (lane & 3)*2 + c;
                    int bn = m / 3, d = m - bn*3;
                    float v = acc[i][j][rh*2 + c];
                    if (useBias) v += g_bias[((bn/NPTS)*3 + d)*R + r];
                    g_Y[(size_t)((bn*G + g)*3 + d)*O + o] = v;
                }
            }
        }
    }
}

// ------------------------- gather + vec-LNA + mean over K (float4) ----------
template<int O, int PPB>
__global__ void __launch_bounds__(256) k_gather(int co)
{
    __shared__ int sidx[PPB*KNN];
    int t  = threadIdx.x;
    int p0 = blockIdx.x * PPB;
    for (int i = t; i < PPB*KNN; i += 256) sidx[i] = g_idx[p0*KNN + i];
    __syncthreads();

    constexpr int TPP = O/4;
    int pl = t / TPP;
    int oc = (t - pl*TPP)*4;
    int bn = p0 + pl;
    int jbase = (bn / NPTS) * NPTS;

    const float* Z = g_Y + (size_t)bn*12*O + oc;
    float4 zp0 = *(const float4*)(Z + 3*O);
    float4 zp1 = *(const float4*)(Z + 4*O);
    float4 zp2 = *(const float4*)(Z + 5*O);
    float4 zq0 = *(const float4*)(Z + 9*O);
    float4 zq1 = *(const float4*)(Z + 10*O);
    float4 zq2 = *(const float4*)(Z + 11*O);
    float a0[4] = {0,0,0,0}, a1[4] = {0,0,0,0}, a2[4] = {0,0,0,0};

    for (int k = 0; k < KNN; k++){
        int j = jbase + sidx[pl*KNN + k];
        const float* Yj = g_Y + (size_t)j*12*O + oc;
        float4 P0 = *(const float4*)(Yj + 0*O);
        float4 P1 = *(const float4*)(Yj + 1*O);
        float4 P2 = *(const float4*)(Yj + 2*O);
        float4 Q0 = *(const float4*)(Yj + 6*O);
        float4 Q1 = *(const float4*)(Yj + 7*O);
        float4 Q2 = *(const float4*)(Yj + 8*O);
        #pragma unroll
        for (int c = 0; c < 4; c++){
            float p0v = (&P0.x)[c] + (&zp0.x)[c];
            float p1v = (&P1.x)[c] + (&zp1.x)[c];
            float p2v = (&P2.x)[c] + (&zp2.x)[c];
            float q0  = (&Q0.x)[c] + (&zq0.x)[c];
            float q1  = (&Q1.x)[c] + (&zq1.x)[c];
            float q2  = (&Q2.x)[c] + (&zq2.x)[c];
            float dot = p0v*q0 + p1v*q1 + p2v*q2;
            float dsq = q0*q0 + q1*q1 + q2*q2;
            float s = (dot < 0.f) ? 0.8f*dot/(dsq + 1e-6f) : 0.f;
            a0[c] += p0v - s*q0; a1[c] += p1v - s*q1; a2[c] += p2v - s*q2;
        }
    }
    float* out = g_xcat240 + (size_t)bn*3*240 + co + oc;
    float4 v0 = {a0[0]*0.0625f, a0[1]*0.0625f, a0[2]*0.0625f, a0[3]*0.0625f};
    float4 v1 = {a1[0]*0.0625f, a1[1]*0.0625f, a1[2]*0.0625f, a1[3]*0.0625f};
    float4 v2 = {a2[0]*0.0625f, a2[1]*0.0625f, a2[2]*0.0625f, a2[3]*0.0625f};
    *(float4*)(out)       = v0;
    *(float4*)(out + 240) = v1;
    *(float4*)(out + 480) = v2;
}

// ------------------------- layer c: dc GEMV (1x240), vec4 --------------------
__global__ void k_dc(const float* __restrict__ wcd)
{
    int gt = blockIdx.x*blockDim.x + threadIdx.x;
    int warp = gt >> 5, lane = gt & 31;
    if (warp >= M_COLS) return;
    const float* row = g_xcat240 + (size_t)warp*240;
    float s = 0.f;
    for (int c = lane; c < 60; c += 32){
        float4 a = *(const float4*)&row[c*4];
        float4 w = *(const float4*)&wcd[c*4];
        s += a.x*w.x + a.y*w.y + a.z*w.z + a.w*w.w;
    }
    #pragma unroll
    for (int off = 16; off; off >>= 1) s += __shfl_xor_sync(0xffffffffu, s, off);
    if (lane == 0) g_dc[warp] = s;
}

// layer c LNA (q shared across o), vec4
__global__ void k_lna_c()
{
    int t = blockIdx.x*blockDim.x + threadIdx.x;
    if (t >= BN_ALL*32) return;
    int bn = t >> 5, oc = (t & 31)*4;
    const float* Yb = g_Y + (size_t)bn*384 + oc;
    float4 P0 = *(const float4*)(Yb);
    float4 P1 = *(const float4*)(Yb + 128);
    float4 P2 = *(const float4*)(Yb + 256);
    float q0 = g_dc[bn*3+0], q1 = g_dc[bn*3+1], q2 = g_dc[bn*3+2];
    float4 O0, O1, O2;
    #pragma unroll
    for (int c = 0; c < 4; c++){
        float o0,o1,o2;
        lna3((&P0.x)[c], (&P1.x)[c], (&P2.x)[c], q0, q1, q2, o0,o1,o2);
        (&O0.x)[c]=o0; (&O1.x)[c]=o1; (&O2.x)[c]=o2;
    }
    float* out = g_xcat256 + (size_t)bn*3*256 + oc;
    *(float4*)(out)       = O0;
    *(float4*)(out + 256) = O1;
    *(float4*)(out + 512) = O2;
}

// ------------------------- xm mean -------------------------------------------
__global__ void k_xm_part()
{
    int blk  = blockIdx.x;
    int slab = blk & 31;
    int bd3  = blk >> 5;
    int b = bd3 / 3, d = bd3 - b*3;
    int o = threadIdx.x;
    float s = 0.f;
    for (int nn = 0; nn < 64; nn++){
        int n = slab*64 + nn;
        s += g_xcat256[((size_t)(b*NPTS+n)*3 + d)*256 + o];
    }
    g_xmp[(size_t)(bd3*32 + slab)*128 + o] = s;
}

__global__ void k_xm_final()
{
    int t = blockIdx.x*blockDim.x + threadIdx.x;
    if (t >= BATCH*3*128) return;
    int bd3 = t >> 7, o = t & 127;
    float s = 0.f;
    for (int sl = 0; sl < 32; sl++) s += g_xmp[(size_t)(bd3*32+sl)*128 + o];
    g_xm[bd3*128 + o] = s * (1.f/2048.f);
}

__global__ void k_bias_i1(const float* __restrict__ wi1f, const float* __restrict__ wi1d)
{
    int t = blockIdx.x*blockDim.x + threadIdx.x;
    if (t >= BATCH*3*256) return;
    int bd3 = t >> 8, r = t & 255;
    const float* wrow = (r < 128) ? (wi1f + r*256) : (wi1d + (r-128)*256);
    float s = 0.f;
    for (int c = 0; c < 128; c++) s = fmaf(wrow[128+c], g_xm[bd3*128 + c], s);
    g_bias[bd3*256 + r] = s;
}

// ------------------------- i1 LNA (writes t128 only) ------------------------
__global__ void k_lna_pd()
{
    int t = blockIdx.x*blockDim.x + threadIdx.x;
    if (t >= BN_ALL*32) return;
    int bn = t >> 5, oc = (t & 31)*4;
    const float* Yb = g_Y + (size_t)bn*768 + oc;
    float4 P0 = *(const float4*)(Yb + 0*128);
    float4 P1 = *(const float4*)(Yb + 1*128);
    float4 P2 = *(const float4*)(Yb + 2*128);
    float4 Q0 = *(const float4*)(Yb + 3*128);
    float4 Q1 = *(const float4*)(Yb + 4*128);
    float4 Q2 = *(const float4*)(Yb + 5*128);
    float4 O0, O1, O2;
    #pragma unroll
    for (int c = 0; c < 4; c++){
        float o0,o1,o2;
        lna3((&P0.x)[c], (&P1.x)[c], (&P2.x)[c],
             (&Q0.x)[c], (&Q1.x)[c], (&Q2.x)[c], o0,o1,o2);
        (&O0.x)[c]=o0; (&O1.x)[c]=o1; (&O2.x)[c]=o2;
    }
    float* out = g_t128 + (size_t)bn*3*128 + oc;
    *(float4*)(out)=O0; *(float4*)(out+128)=O1; *(float4*)(out+256)=O2;
}

// ------------------------- final invariant (fused i2-LNA + dot) --------------
__global__ void __launch_bounds__(256) k_inv(float* __restrict__ out)
{
    __shared__ float tile[256*33];
    int n0 = blockIdx.x * 32;
    int b  = n0 / NPTS;
    int t  = threadIdx.x;
    int pg = t >> 6;             // 0..3 -> 8 points each
    int oc = (t & 63)*4;         // 4 o-channels
    bool hi = (oc >= 128);
    float4 a0c, a1c, a2c;
    if (hi){
        a0c = *(const float4*)&g_xm[(b*3+0)*128 + oc - 128];
        a1c = *(const float4*)&g_xm[(b*3+1)*128 + oc - 128];
        a2c = *(const float4*)&g_xm[(b*3+2)*128 + oc - 128];
    }
    for (int pp = 0; pp < 8; pp++){
        int p = pg*8 + pp;
        int bn = n0 + p;
        size_t base = (size_t)bn*3*256 + oc;
        float4 a0, a1, a2;
        if (hi){ a0 = a0c; a1 = a1c; a2 = a2c; }
        else {
            a0 = *(const float4*)&g_xcat256[base];
            a1 = *(const float4*)&g_xcat256[base + 256];
            a2 = *(const float4*)&g_xcat256[base + 512];
        }
        const float* Yb = g_Y + (size_t)bn*1536 + oc;
        float4 P0 = *(const float4*)(Yb + 0*256);
        float4 P1 = *(const float4*)(Yb + 1*256);
        float4 P2 = *(const float4*)(Yb + 2*256);
        float4 Q0 = *(const float4*)(Yb + 3*256);
        float4 Q1 = *(const float4*)(Yb + 4*256);
        float4 Q2 = *(const float4*)(Yb + 5*256);
        #pragma unroll
        for (int c = 0; c < 4; c++){
            float o0,o1,o2;
            lna3((&P0.x)[c], (&P1.x)[c], (&P2.x)[c],
                 (&Q0.x)[c], (&Q1.x)[c], (&Q2.x)[c], o0,o1,o2);
            float s = (&a0.x)[c]*o0 + (&a1.x)[c]*o1 + (&a2.x)[c]*o2;
            tile[(oc + c)*33 + p] = s;
        }
    }
    __syncthreads();
    int nn0 = n0 - b*NPTS;
    int p   = t & 31, og = t >> 5;
    for (int o = og; o < 256; o += 8)
        out[(size_t)(b*256 + o)*NPTS + nn0 + p] = tile[o*33 + p];
}

// ------------------------- launcher -----------------------------------------
extern "C" void kernel_launch(void* const* d_in, const int* in_sizes, int n_in,
                              void* d_out, int out_size)
{
    const float* x    = (const float*)d_in[0];
    const float* w1f  = (const float*)d_in[1];
    const float* w1d  = (const float*)d_in[2];
    const float* w2f  = (const float*)d_in[3];
    const float* w2d  = (const float*)d_in[4];
    const float* w3f  = (const float*)d_in[5];
    const float* w3d  = (const float*)d_in[6];
    const float* w4f  = (const float*)d_in[7];
    const float* w4d  = (const float*)d_in[8];
    const float* wcf  = (const float*)d_in[9];
    const float* wcd  = (const float*)d_in[10];
    const float* wi1f = (const float*)d_in[11];
    const float* wi1d = (const float*)d_in[12];
    const float* wi2f = (const float*)d_in[13];
    const float* wi2d = (const float*)d_in[14];
    float* out = (float*)d_out;

    // all weight prep in one launch, up front
    k_wcomb_all<<<(W_TOT+255)/256, 256>>>(w2f, w2d, w3f, w3d, w4f, w4d,
                                          wcf, wi1f, wi1d, wi2f, wi2d);

    k_prep<<<(BN_ALL+127)/128, 128>>>(x);
    k_knn_part<<<(BN_ALL*4+63)/64, 64>>>();
    k_knn_merge<<<(BN_ALL+31)/32, 32>>>();

    // ---- layer 1 (C=1 -> O=16)
    k_layer1<<<(BN_ALL*48+255)/256, 256>>>(w1f, w1d);
    k_gather<16,64><<<BN_ALL/64, 256>>>(0);

    // ---- layer 2 (C=16 -> O=32)
    k_hgemm<<<dim3(M_COLS/128, 1), 256>>>(0, 0, WOF_L2, 128, 16, 240, 0, 4, 32);
    k_gather<32,32><<<BN_ALL/32, 256>>>(16);

    // ---- layer 3 (C=32 -> O=64)
    k_hgemm<<<dim3(M_COLS/128, 2), 256>>>(0, 0, WOF_L3, 256, 32, 240, 16, 4, 64);
    k_gather<64,16><<<BN_ALL/16, 256>>>(48);

    // ---- layer 4 (C=64 -> O=128)
    k_hgemm<<<dim3(M_COLS/128, 4), 256>>>(0, 0, WOF_L4, 512, 64, 240, 48, 4, 128);
    k_gather<128,8><<<BN_ALL/8, 256>>>(112);

    // ---- concat layer (wcf 128x240, wcd 1x240)
    k_hgemm<<<dim3(M_COLS/128, 1), 256>>>(0, 0, WOF_C, 128, 240, 240, 0, 1, 128);
    k_dc<<<(M_COLS*32+255)/256, 256>>>(wcd);
    k_lna_c<<<(BN_ALL*32+255)/256, 256>>>();

    // ---- xm mean over N
    k_xm_part<<<BATCH*3*32, 128>>>();
    k_xm_final<<<(BATCH*3*128+255)/256, 256>>>();

    // ---- i1 (wi1f/wi1d 128x256; contract 128 + xm bias)
    k_bias_i1<<<(BATCH*3*256+255)/256, 256>>>(wi1f, wi1d);
    k_hgemm<<<dim3(M_COLS/128, 2), 256>>>(1, 1, WOF_I1, 256, 128, 256, 0, 2, 128);
    k_lna_pd<<<(BN_ALL*32+255)/256, 256>>>();

    // ---- i2 (wi2f/wi2d 256x128) -> LNA fused into k_inv
    k_hgemm<<<dim3(M_COLS/128, 4), 256>>>(2, 0, WOF_I2, 512, 128, 128, 0, 2, 256);

    // ---- invariant output (B,256,N)
    k_inv<<<BN_ALL/32, 256>>>(out);
}

// round 14
// speedup vs baseline: 1.0182x; 1.0182x over previous
#include <cuda_runtime.h>
#include <cuda_bf16.h>
#include <cstdint>

#define BATCH 4
#define NPTS  2048
#define KNN   16
#define BN_ALL (BATCH*NPTS)      // 8192
#define M_COLS (BN_ALL*3)        // 24576

// weight buffer offsets (elements)
#define WOF_L2 0
#define WOF_L3 2048
#define WOF_L4 10240
#define WOF_C  43008
#define WOF_I1 73728
#define WOF_I2 106496
#define W_TOT  172032

// ------------------------- scratch (device globals; no mallocs) -------------
static __device__ __align__(16) float g_X0[BN_ALL*3];
static __device__ __align__(16) float4 g_pts4[BN_ALL];   // (x,y,z,|x|^2)
static __device__ int   g_idx[BN_ALL*KNN];
static __device__ __align__(16) float g_knnd[BN_ALL*64];
static __device__ __align__(16) int   g_knni[BN_ALL*64];
static __device__ __align__(16) float g_xcat240[BN_ALL*3*240];
static __device__ __align__(16) float g_xcat256[BN_ALL*3*256];
static __device__ __align__(16) float g_t128 [BN_ALL*3*128];
static __device__ __align__(16) float g_Y    [BN_ALL*1536];   // reused per layer
static __device__ float g_dc  [M_COLS];
static __device__ float g_xm  [BATCH*3*128];
static __device__ float g_xmp [BATCH*3*32*128];
static __device__ float g_bias[BATCH*3*512];
static __device__ __align__(16) __nv_bfloat16 g_Wh[W_TOT];
static __device__ __align__(16) __nv_bfloat16 g_Wl[W_TOT];

// ------------------------- helpers ------------------------------------------
__device__ __forceinline__ void lna3(float p0,float p1,float p2,
                                     float q0,float q1,float q2,
                                     float&o0,float&o1,float&o2)
{
    float dot = p0*q0 + p1*q1 + p2*q2;
    float dsq = q0*q0 + q1*q1 + q2*q2;
    float s = (dot < 0.f) ? 0.8f*dot/(dsq + 1e-6f) : 0.f;
    o0 = p0 - s*q0; o1 = p1 - s*q1; o2 = p2 - s*q2;
}

__device__ __forceinline__ uint32_t cvt2bf(float x, float y, bool lo)
{
    __nv_bfloat16 hx = __float2bfloat16(x), hy = __float2bfloat16(y);
    if (lo){
        hx = __float2bfloat16(x - __bfloat162float(hx));
        hy = __float2bfloat16(y - __bfloat162float(hy));
    }
    __nv_bfloat162 p; p.x = hx; p.y = hy;
    return *(uint32_t*)&p;
}

// ------------------------- prep / KNN ----------------------------------------
__global__ void k_prep(const float* __restrict__ x)
{
    int i = blockIdx.x*blockDim.x + threadIdx.x;
    if (i >= BN_ALL) return;
    int b = i / NPTS, n = i - b*NPTS;
    float vx = x[(b*3+0)*NPTS + n];
    float vy = x[(b*3+1)*NPTS + n];
    float vz = x[(b*3+2)*NPTS + n];
    g_X0[i*3+0]=vx; g_X0[i*3+1]=vy; g_X0[i*3+2]=vz;
    float sq = fmaf(vz,vz, fmaf(vy,vy, vx*vx));
    float4 p; p.x=vx; p.y=vy; p.z=vz; p.w=sq;
    g_pts4[i] = p;
}

__global__ void k_knn_part()
{
    int t = blockIdx.x*blockDim.x + threadIdx.x;
    if (t >= BN_ALL*4) return;
    int bn    = t & (BN_ALL-1);
    int chunk = t >> 13;
    int b = bn / NPTS;
    float4 pv = g_pts4[bn];
    float px = pv.x, py = pv.y, pz = pv.z, sn = pv.w;
    const float4* Pb = g_pts4 + b*NPTS;

    float bd[KNN]; int bi[KNN];
    #pragma unroll
    for (int i = 0; i < KNN; i++){ bd[i] = 3.4e38f; bi[i] = 0; }
    float worst = 3.4e38f;     // register copy of bd[KNN-1] -> no local-mem load on hot path
    int m0 = chunk*512;
    #pragma unroll 4
    for (int mm = 0; mm < 512; mm++){
        int m = m0 + mm;
        float4 c = Pb[m];
        float dot = fmaf(pz,c.z, fmaf(py,c.y, px*c.x));
        float d2  = (sn + c.w) - 2.f*dot;
        if (d2 < worst){
            int p = KNN-1;
            while (p > 0 && bd[p-1] > d2){ bd[p]=bd[p-1]; bi[p]=bi[p-1]; p--; }
            bd[p] = d2; bi[p] = m;
            worst = bd[KNN-1];
        }
    }
    float* od = g_knnd + bn*64 + chunk*16;
    int*   oi = g_knni + bn*64 + chunk*16;
    #pragma unroll
    for (int i = 0; i < 4; i++){
        float4 vd = { bd[i*4], bd[i*4+1], bd[i*4+2], bd[i*4+3] };
        int4   vi = { bi[i*4], bi[i*4+1], bi[i*4+2], bi[i*4+3] };
        *(float4*)(od + i*4) = vd;
        *(int4*)(oi + i*4)   = vi;
    }
}

// 4-way head-pointer merge: 16 rounds of min-of-4-heads (tie -> lowest chunk).
// Runs are ascending, chunk-ordered, so this reproduces the insertion-sort
// result bit-exactly, with NO dynamically-indexed local arrays.
__global__ void k_knn_merge()
{
    int bn = blockIdx.x*blockDim.x + threadIdx.x;
    if (bn >= BN_ALL) return;
    const float* cd = g_knnd + bn*64;
    const int*   ci = g_knni + bn*64;
    int h0 = 0, h1 = 0, h2 = 0, h3 = 0;
    float d0 = cd[0], d1 = cd[16], d2 = cd[32], d3 = cd[48];
    int* out = g_idx + bn*KNN;
    #pragma unroll
    for (int i = 0; i < KNN; i++){
        // min with tie -> lowest chunk (strict < for later chunks)
        float best = d0; int sel = 0;
        if (d1 < best){ best = d1; sel = 1; }
        if (d2 < best){ best = d2; sel = 2; }
        if (d3 < best){ best = d3; sel = 3; }
        int idx;
        if      (sel == 0){ idx = ci[h0];      h0++; d0 = cd[h0]; }
        else if (sel == 1){ idx = ci[16 + h1]; h1++; d1 = cd[16 + h1]; }
        else if (sel == 2){ idx = ci[32 + h2]; h2++; d2 = cd[32 + h2]; }
        else              { idx = ci[48 + h3]; h3++; d3 = cd[48 + h3]; }
        out[i] = idx;
    }
}

// ------------------------- layer 1 direct Y build (C=1, O=16), vec4 ---------
__global__ void k_layer1(const float* __restrict__ w1f, const float* __restrict__ w1d)
{
    int t = blockIdx.x*blockDim.x + threadIdx.x;
    if (t >= BN_ALL*48) return;
    int bn = t / 48, r = t - bn*48;
    int pl = r >> 2, o4 = (r & 3)*4;
    int g = pl / 3, d = pl - g*3;
    float xv = g_X0[bn*3 + d];
    const float* W = (g < 2) ? w1f : w1d;
    float4 wa = *(const float4*)&W[o4*2];
    float4 wb = *(const float4*)&W[o4*2 + 4];
    float4 out;
    if ((g & 1) == 0){
        out.x = wa.x*xv; out.y = wa.z*xv; out.z = wb.x*xv; out.w = wb.z*xv;
    } else {
        out.x = (wa.y-wa.x)*xv; out.y = (wa.w-wa.z)*xv;
        out.z = (wb.y-wb.x)*xv; out.w = (wb.w-wb.z)*xv;
    }
    *(float4*)&g_Y[(size_t)bn*192 + pl*16 + o4] = out;
}

// ------------------------- ONE combined weight-combine kernel ---------------
__device__ __forceinline__ void split_store(size_t idx, float v)
{
    __nv_bfloat16 h = __float2bfloat16(v);
    g_Wh[idx] = h;
    g_Wl[idx] = __float2bfloat16(v - __bfloat162float(h));
}

__device__ __forceinline__ float graph_w(const float* Wf, const float* Wd,
                                         int C, int O, int local)
{
    int r = local / C, c = local - r*C;
    int g = r / O, o = r - g*O;
    if (g == 0) return Wf[o*2*C + c];
    if (g == 1) return Wf[o*2*C + C + c] - Wf[o*2*C + c];
    if (g == 2) return Wd[o*2*C + c];
    return Wd[o*2*C + C + c] - Wd[o*2*C + c];
}

__global__ void k_wcomb_all(const float* __restrict__ w2f, const float* __restrict__ w2d,
                            const float* __restrict__ w3f, const float* __restrict__ w3d,
                            const float* __restrict__ w4f, const float* __restrict__ w4d,
                            const float* __restrict__ wcf,
                            const float* __restrict__ wi1f, const float* __restrict__ wi1d,
                            const float* __restrict__ wi2f, const float* __restrict__ wi2d)
{
    int t = blockIdx.x*blockDim.x + threadIdx.x;
    if (t >= W_TOT) return;
    float v;
    if (t < WOF_L3)      v = graph_w(w2f, w2d, 16, 32,  t - WOF_L2);
    else if (t < WOF_L4) v = graph_w(w3f, w3d, 32, 64,  t - WOF_L3);
    else if (t < WOF_C)  v = graph_w(w4f, w4d, 64, 128, t - WOF_L4);
    else if (t < WOF_I1) v = wcf[t - WOF_C];
    else if (t < WOF_I2){
        int l = t - WOF_I1, r = l >> 7, c = l & 127;
        v = (r < 128) ? wi1f[r*256 + c] : wi1d[(r-128)*256 + c];
    } else {
        int l = t - WOF_I2, r = l >> 7, c = l & 127;
        v = (r < 256) ? wi2f[r*128 + c] : wi2d[(r-256)*128 + c];
    }
    split_store(t, v);
}

// ------------------------- warp-MMA GEMM (double-buffered) ------------------
#define SWZ(off) ((off) ^ (((off)>>3)&0x30))

__device__ __forceinline__ void ldsm_x4(uint32_t* a, uint32_t addr)
{
    asm volatile("ldmatrix.sync.aligned.m8n8.x4.shared.b16 {%0,%1,%2,%3}, [%4];"
        : "=r"(a[0]),"=r"(a[1]),"=r"(a[2]),"=r"(a[3]) : "r"(addr));
}
__device__ __forceinline__ void ldsm_x2(uint32_t* b, uint32_t addr)
{
    asm volatile("ldmatrix.sync.aligned.m8n8.x2.shared.b16 {%0,%1}, [%2];"
        : "=r"(b[0]),"=r"(b[1]) : "r"(addr));
}
__device__ __forceinline__ void mma16816(float* d, const uint32_t* a, const uint32_t* b)
{
    asm volatile("mma.sync.aligned.m16n8k16.row.col.f32.bf16.bf16.f32 "
        "{%0,%1,%2,%3}, {%4,%5,%6,%7}, {%8,%9}, {%0,%1,%2,%3};"
        : "+f"(d[0]),"+f"(d[1]),"+f"(d[2]),"+f"(d[3])
        : "r"(a[0]),"r"(a[1]),"r"(a[2]),"r"(a[3]),"r"(b[0]),"r"(b[1]));
}

__global__ void __launch_bounds__(256) k_hgemm(int xsel, int useBias, int wofs,
                                               int R, int C, int CS, int co,
                                               int G, int O)
{
    __shared__ __align__(16) char sA[2][128*64];
    __shared__ __align__(16) char sB[2][128*64];
    const float* __restrict__ X = (xsel==0) ? g_xcat240 : (xsel==1) ? g_xcat256 : g_t128;

    int tid  = threadIdx.x, lane = tid & 31, warp = tid >> 5;
    int m0   = blockIdx.x*128, r0 = blockIdx.y*128;
    int nch  = (C + 31) >> 5;
    int EXT  = 3*nch;
    int wr   = (warp >> 2)*64;
    int wm   = (warp & 3)*32;

    int srow = tid >> 1, shalf = tid & 1;

    float acc[4][4][4];
    #pragma unroll
    for (int i=0;i<4;i++)
        #pragma unroll
        for (int j=0;j<4;j++)
            #pragma unroll
            for (int k=0;k<4;k++) acc[i][j][k]=0.f;

    uint4 aS0, aS1, bS0, bS1;

    auto stage = [&](int e){
        int term = e / nch, cblk = e - term*nch;
        bool valid = (cblk*32 + shalf*16) < C;
        const uint4 z = {0,0,0,0};
        if (valid){
            const __nv_bfloat16* Wsrc = (term == 1) ? g_Wl : g_Wh;
            const uint4* p = (const uint4*)&Wsrc[wofs + (size_t)(r0+srow)*C + cblk*32 + shalf*16];
            aS0 = p[0]; aS1 = p[1];
            bool lo = (term == 2);
            const float4* q = (const float4*)&X[(size_t)(m0+srow)*CS + co + cblk*32 + shalf*16];
            float4 f0=q[0], f1=q[1], f2=q[2], f3=q[3];
            bS0.x = cvt2bf(f0.x,f0.y,lo); bS0.y = cvt2bf(f0.z,f0.w,lo);
            bS0.z = cvt2bf(f1.x,f1.y,lo); bS0.w = cvt2bf(f1.z,f1.w,lo);
            bS1.x = cvt2bf(f2.x,f2.y,lo); bS1.y = cvt2bf(f2.z,f2.w,lo);
            bS1.z = cvt2bf(f3.x,f3.y,lo); bS1.w = cvt2bf(f3.z,f3.w,lo);
        } else { aS0=aS1=bS0=bS1=z; }
    };
    auto commit = [&](int buf){
        uint32_t o0 = SWZ((uint32_t)(srow*64 + (shalf*2  )*16));
        uint32_t o1 = SWZ((uint32_t)(srow*64 + (shalf*2+1)*16));
        *(uint4*)(sA[buf]+o0) = aS0;  *(uint4*)(sA[buf]+o1) = aS1;
        *(uint4*)(sB[buf]+o0) = bS0;  *(uint4*)(sB[buf]+o1) = bS1;
    };

    stage(0); commit(0); __syncthreads();

    for (int e = 0; e < EXT; e++){
        if (e+1 < EXT) stage(e+1);
        int buf = e & 1;
        uint32_t baseA = (uint32_t)__cvta_generic_to_shared(sA[buf]);
        uint32_t baseB = (uint32_t)__cvta_generic_to_shared(sB[buf]);
        #pragma unroll
        for (int ks = 0; ks < 32; ks += 16){
            uint32_t a[4][4], b[4][2];
            #pragma unroll
            for (int i = 0; i < 4; i++){
                uint32_t off = (uint32_t)((wr + i*16 + (lane & 15))*64 + ks*2 + (lane >> 4)*16);
                ldsm_x4(a[i], baseA + SWZ(off));
            }
            #pragma unroll
            for (int j = 0; j < 4; j++){
                uint32_t off = (uint32_t)((wm + j*8 + (lane & 7))*64 + ks*2 + ((lane >> 3) & 1)*16);
                ldsm_x2(b[j], baseB + SWZ(off));
            }
            #pragma unroll
            for (int i = 0; i < 4; i++)
                #pragma unroll
                for (int j = 0; j < 4; j++)
                    mma16816(acc[i][j], a[i], b[j]);
        }
        if (e+1 < EXT) commit((e+1) & 1);
        __syncthreads();
    }

    #pragma unroll
    for (int i = 0; i < 4; i++){
        #pragma unroll
        for (int rh = 0; rh < 2; rh++){
            int r = r0 + wr + i*16 + (lane >> 2) + rh*8;
            int g = r / O, o = r - g*O;
            #pragma unroll
            for (int j = 0; j < 4; j++){
                #pragma unroll
                for (int c = 0; c < 2; c++){
                    int m  = m0 + wm + j*8 + (lane & 3)*2 + c;
                    int bn = m / 3, d = m - bn*3;
                    float v = acc[i][j][rh*2 + c];
                    if (useBias) v += g_bias[((bn/NPTS)*3 + d)*R + r];
                    g_Y[(size_t)((bn*G + g)*3 + d)*O + o] = v;
                }
            }
        }
    }
}

// ------------------------- gather + vec-LNA + mean over K (float4) ----------
template<int O, int PPB>
__global__ void __launch_bounds__(256) k_gather(int co)
{
    __shared__ int sidx[PPB*KNN];
    int t  = threadIdx.x;
    int p0 = blockIdx.x * PPB;
    for (int i = t; i < PPB*KNN; i += 256) sidx[i] = g_idx[p0*KNN + i];
    __syncthreads();

    constexpr int TPP = O/4;
    int pl = t / TPP;
    int oc = (t - pl*TPP)*4;
    int bn = p0 + pl;
    int jbase = (bn / NPTS) * NPTS;

    const float* Z = g_Y + (size_t)bn*12*O + oc;
    float4 zp0 = *(const float4*)(Z + 3*O);
    float4 zp1 = *(const float4*)(Z + 4*O);
    float4 zp2 = *(const float4*)(Z + 5*O);
    float4 zq0 = *(const float4*)(Z + 9*O);
    float4 zq1 = *(const float4*)(Z + 10*O);
    float4 zq2 = *(const float4*)(Z + 11*O);
    float a0[4] = {0,0,0,0}, a1[4] = {0,0,0,0}, a2[4] = {0,0,0,0};

    for (int k = 0; k < KNN; k++){
        int j = jbase + sidx[pl*KNN + k];
        const float* Yj = g_Y + (size_t)j*12*O + oc;
        float4 P0 = *(const float4*)(Yj + 0*O);
        float4 P1 = *(const float4*)(Yj + 1*O);
        float4 P2 = *(const float4*)(Yj + 2*O);
        float4 Q0 = *(const float4*)(Yj + 6*O);
        float4 Q1 = *(const float4*)(Yj + 7*O);
        float4 Q2 = *(const float4*)(Yj + 8*O);
        #pragma unroll
        for (int c = 0; c < 4; c++){
            float p0v = (&P0.x)[c] + (&zp0.x)[c];
            float p1v = (&P1.x)[c] + (&zp1.x)[c];
            float p2v = (&P2.x)[c] + (&zp2.x)[c];
            float q0  = (&Q0.x)[c] + (&zq0.x)[c];
            float q1  = (&Q1.x)[c] + (&zq1.x)[c];
            float q2  = (&Q2.x)[c] + (&zq2.x)[c];
            float dot = p0v*q0 + p1v*q1 + p2v*q2;
            float dsq = q0*q0 + q1*q1 + q2*q2;
            float s = (dot < 0.f) ? 0.8f*dot/(dsq + 1e-6f) : 0.f;
            a0[c] += p0v - s*q0; a1[c] += p1v - s*q1; a2[c] += p2v - s*q2;
        }
    }
    float* out = g_xcat240 + (size_t)bn*3*240 + co + oc;
    float4 v0 = {a0[0]*0.0625f, a0[1]*0.0625f, a0[2]*0.0625f, a0[3]*0.0625f};
    float4 v1 = {a1[0]*0.0625f, a1[1]*0.0625f, a1[2]*0.0625f, a1[3]*0.0625f};
    float4 v2 = {a2[0]*0.0625f, a2[1]*0.0625f, a2[2]*0.0625f, a2[3]*0.0625f};
    *(float4*)(out)       = v0;
    *(float4*)(out + 240) = v1;
    *(float4*)(out + 480) = v2;
}

// ------------------------- layer c: dc GEMV (1x240), vec4 --------------------
__global__ void k_dc(const float* __restrict__ wcd)
{
    int gt = blockIdx.x*blockDim.x + threadIdx.x;
    int warp = gt >> 5, lane = gt & 31;
    if (warp >= M_COLS) return;
    const float* row = g_xcat240 + (size_t)warp*240;
    float s = 0.f;
    for (int c = lane; c < 60; c += 32){
        float4 a = *(const float4*)&row[c*4];
        float4 w = *(const float4*)&wcd[c*4];
        s += a.x*w.x + a.y*w.y + a.z*w.z + a.w*w.w;
    }
    #pragma unroll
    for (int off = 16; off; off >>= 1) s += __shfl_xor_sync(0xffffffffu, s, off);
    if (lane == 0) g_dc[warp] = s;
}

// layer c LNA (q shared across o), vec4
__global__ void k_lna_c()
{
    int t = blockIdx.x*blockDim.x + threadIdx.x;
    if (t >= BN_ALL*32) return;
    int bn = t >> 5, oc = (t & 31)*4;
    const float* Yb = g_Y + (size_t)bn*384 + oc;
    float4 P0 = *(const float4*)(Yb);
    float4 P1 = *(const float4*)(Yb + 128);
    float4 P2 = *(const float4*)(Yb + 256);
    float q0 = g_dc[bn*3+0], q1 = g_dc[bn*3+1], q2 = g_dc[bn*3+2];
    float4 O0, O1, O2;
    #pragma unroll
    for (int c = 0; c < 4; c++){
        float o0,o1,o2;
        lna3((&P0.x)[c], (&P1.x)[c], (&P2.x)[c], q0, q1, q2, o0,o1,o2);
        (&O0.x)[c]=o0; (&O1.x)[c]=o1; (&O2.x)[c]=o2;
    }
    float* out = g_xcat256 + (size_t)bn*3*256 + oc;
    *(float4*)(out)       = O0;
    *(float4*)(out + 256) = O1;
    *(float4*)(out + 512) = O2;
}

// ------------------------- xm mean -------------------------------------------
__global__ void k_xm_part()
{
    int blk  = blockIdx.x;
    int slab = blk & 31;
    int bd3  = blk >> 5;
    int b = bd3 / 3, d = bd3 - b*3;
    int o = threadIdx.x;
    float s = 0.f;
    for (int nn = 0; nn < 64; nn++){
        int n = slab*64 + nn;
        s += g_xcat256[((size_t)(b*NPTS+n)*3 + d)*256 + o];
    }
    g_xmp[(size_t)(bd3*32 + slab)*128 + o] = s;
}

__global__ void k_xm_final()
{
    int t = blockIdx.x*blockDim.x + threadIdx.x;
    if (t >= BATCH*3*128) return;
    int bd3 = t >> 7, o = t & 127;
    float s = 0.f;
    for (int sl = 0; sl < 32; sl++) s += g_xmp[(size_t)(bd3*32+sl)*128 + o];
    g_xm[bd3*128 + o] = s * (1.f/2048.f);
}

__global__ void k_bias_i1(const float* __restrict__ wi1f, const float* __restrict__ wi1d)
{
    int t = blockIdx.x*blockDim.x + threadIdx.x;
    if (t >= BATCH*3*256) return;
    int bd3 = t >> 8, r = t & 255;
    const float* wrow = (r < 128) ? (wi1f + r*256) : (wi1d + (r-128)*256);
    float s = 0.f;
    for (int c = 0; c < 128; c++) s = fmaf(wrow[128+c], g_xm[bd3*128 + c], s);
    g_bias[bd3*256 + r] = s;
}

// ------------------------- i1 LNA (writes t128 only) ------------------------
__global__ void k_lna_pd()
{
    int t = blockIdx.x*blockDim.x + threadIdx.x;
    if (t >= BN_ALL*32) return;
    int bn = t >> 5, oc = (t & 31)*4;
    const float* Yb = g_Y + (size_t)bn*768 + oc;
    float4 P0 = *(const float4*)(Yb + 0*128);
    float4 P1 = *(const float4*)(Yb + 1*128);
    float4 P2 = *(const float4*)(Yb + 2*128);
    float4 Q0 = *(const float4*)(Yb + 3*128);
    float4 Q1 = *(const float4*)(Yb + 4*128);
    float4 Q2 = *(const float4*)(Yb + 5*128);
    float4 O0, O1, O2;
    #pragma unroll
    for (int c = 0; c < 4; c++){
        float o0,o1,o2;
        lna3((&P0.x)[c], (&P1.x)[c], (&P2.x)[c],
             (&Q0.x)[c], (&Q1.x)[c], (&Q2.x)[c], o0,o1,o2);
        (&O0.x)[c]=o0; (&O1.x)[c]=o1; (&O2.x)[c]=o2;
    }
    float* out = g_t128 + (size_t)bn*3*128 + oc;
    *(float4*)(out)=O0; *(float4*)(out+128)=O1; *(float4*)(out+256)=O2;
}

// ------------------------- final invariant (fused i2-LNA + dot) --------------
__global__ void __launch_bounds__(256) k_inv(float* __restrict__ out)
{
    __shared__ float tile[256*33];
    int n0 = blockIdx.x * 32;
    int b  = n0 / NPTS;
    int t  = threadIdx.x;
    int pg = t >> 6;             // 0..3 -> 8 points each
    int oc = (t & 63)*4;         // 4 o-channels
    bool hi = (oc >= 128);
    float4 a0c, a1c, a2c;
    if (hi){
        a0c = *(const float4*)&g_xm[(b*3+0)*128 + oc - 128];
        a1c = *(const float4*)&g_xm[(b*3+1)*128 + oc - 128];
        a2c = *(const float4*)&g_xm[(b*3+2)*128 + oc - 128];
    }
    for (int pp = 0; pp < 8; pp++){
        int p = pg*8 + pp;
        int bn = n0 + p;
        size_t base = (size_t)bn*3*256 + oc;
        float4 a0, a1, a2;
        if (hi){ a0 = a0c; a1 = a1c; a2 = a2c; }
        else {
            a0 = *(const float4*)&g_xcat256[base];
            a1 = *(const float4*)&g_xcat256[base + 256];
            a2 = *(const float4*)&g_xcat256[base + 512];
        }
        const float* Yb = g_Y + (size_t)bn*1536 + oc;
        float4 P0 = *(const float4*)(Yb + 0*256);
        float4 P1 = *(const float4*)(Yb + 1*256);
        float4 P2 = *(const float4*)(Yb + 2*256);
        float4 Q0 = *(const float4*)(Yb + 3*256);
        float4 Q1 = *(const float4*)(Yb + 4*256);
        float4 Q2 = *(const float4*)(Yb + 5*256);
        #pragma unroll
        for (int c = 0; c < 4; c++){
            float o0,o1,o2;
            lna3((&P0.x)[c], (&P1.x)[c], (&P2.x)[c],
                 (&Q0.x)[c], (&Q1.x)[c], (&Q2.x)[c], o0,o1,o2);
            float s = (&a0.x)[c]*o0 + (&a1.x)[c]*o1 + (&a2.x)[c]*o2;
            tile[(oc + c)*33 + p] = s;
        }
    }
    __syncthreads();
    int nn0 = n0 - b*NPTS;
    int p   = t & 31, og = t >> 5;
    for (int o = og; o < 256; o += 8)
        out[(size_t)(b*256 + o)*NPTS + nn0 + p] = tile[o*33 + p];
}

// ------------------------- launcher -----------------------------------------
extern "C" void kernel_launch(void* const* d_in, const int* in_sizes, int n_in,
                              void* d_out, int out_size)
{
    const float* x    = (const float*)d_in[0];
    const float* w1f  = (const float*)d_in[1];
    const float* w1d  = (const float*)d_in[2];
    const float* w2f  = (const float*)d_in[3];
    const float* w2d  = (const float*)d_in[4];
    const float* w3f  = (const float*)d_in[5];
    const float* w3d  = (const float*)d_in[6];
    const float* w4f  = (const float*)d_in[7];
    const float* w4d  = (const float*)d_in[8];
    const float* wcf  = (const float*)d_in[9];
    const float* wcd  = (const float*)d_in[10];
    const float* wi1f = (const float*)d_in[11];
    const float* wi1d = (const float*)d_in[12];
    const float* wi2f = (const float*)d_in[13];
    const float* wi2d = (const float*)d_in[14];
    float* out = (float*)d_out;

    // all weight prep in one launch, up front
    k_wcomb_all<<<(W_TOT+255)/256, 256>>>(w2f, w2d, w3f, w3d, w4f, w4d,
                                          wcf, wi1f, wi1d, wi2f, wi2d);

    k_prep<<<(BN_ALL+127)/128, 128>>>(x);
    k_knn_part<<<(BN_ALL*4+127)/128, 128>>>();
    k_knn_merge<<<(BN_ALL+127)/128, 128>>>();

    // ---- layer 1 (C=1 -> O=16)
    k_layer1<<<(BN_ALL*48+255)/256, 256>>>(w1f, w1d);
    k_gather<16,64><<<BN_ALL/64, 256>>>(0);

    // ---- layer 2 (C=16 -> O=32)
    k_hgemm<<<dim3(M_COLS/128, 1), 256>>>(0, 0, WOF_L2, 128, 16, 240, 0, 4, 32);
    k_gather<32,32><<<BN_ALL/32, 256>>>(16);

    // ---- layer 3 (C=32 -> O=64)
    k_hgemm<<<dim3(M_COLS/128, 2), 256>>>(0, 0, WOF_L3, 256, 32, 240, 16, 4, 64);
    k_gather<64,16><<<BN_ALL/16, 256>>>(48);

    // ---- layer 4 (C=64 -> O=128)
    k_hgemm<<<dim3(M_COLS/128, 4), 256>>>(0, 0, WOF_L4, 512, 64, 240, 48, 4, 128);
    k_gather<128,8><<<BN_ALL/8, 256>>>(112);

    // ---- concat layer (wcf 128x240, wcd 1x240)
    k_hgemm<<<dim3(M_COLS/128, 1), 256>>>(0, 0, WOF_C, 128, 240, 240, 0, 1, 128);
    k_dc<<<(M_COLS*32+255)/256, 256>>>(wcd);
    k_lna_c<<<(BN_ALL*32+255)/256, 256>>>();

    // ---- xm mean over N
    k_xm_part<<<BATCH*3*32, 128>>>();
    k_xm_final<<<(BATCH*3*128+255)/256, 256>>>();

    // ---- i1 (wi1f/wi1d 128x256; contract 128 + xm bias)
    k_bias_i1<<<(BATCH*3*256+255)/256, 256>>>(wi1f, wi1d);
    k_hgemm<<<dim3(M_COLS/128, 2), 256>>>(1, 1, WOF_I1, 256, 128, 256, 0, 2, 128);
    k_lna_pd<<<(BN_ALL*32+255)/256, 256>>>();

    // ---- i2 (wi2f/wi2d 256x128) -> LNA fused into k_inv
    k_hgemm<<<dim3(M_COLS/128, 4), 256>>>(2, 0, WOF_I2, 512, 128, 128, 0, 2, 256);

    // ---- invariant output (B,256,N)
    k_inv<<<BN_ALL/32, 256>>>(out);
}

// round 15
// speedup vs baseline: 1.0761x; 1.0569x over previous
#include <cuda_runtime.h>
#include <cuda_bf16.h>
#include <cstdint>

#define BATCH 4
#define NPTS  2048
#define KNN   16
#define BN_ALL (BATCH*NPTS)      // 8192
#define M_COLS (BN_ALL*3)        // 24576

// weight buffer offsets (elements)
#define WOF_L2 0
#define WOF_L3 2048
#define WOF_L4 10240
#define WOF_C  43008
#define WOF_I1 73728
#define WOF_I2 106496
#define W_TOT  172032

// ------------------------- scratch (device globals; no mallocs) -------------
static __device__ __align__(16) float g_X0[BN_ALL*3];
static __device__ __align__(16) float4 g_pts4[BN_ALL];   // (x,y,z,|x|^2)
static __device__ int   g_idx[BN_ALL*KNN];
static __device__ __align__(16) float g_knnd[BN_ALL*64];
static __device__ __align__(16) int   g_knni[BN_ALL*64];
static __device__ __align__(16) float g_xcat240[BN_ALL*3*240];
static __device__ __align__(16) float g_xcat256[BN_ALL*3*256];
static __device__ __align__(16) float g_t128 [BN_ALL*3*128];
static __device__ __align__(16) float g_Y    [BN_ALL*1536];   // reused per layer
static __device__ float g_dc  [M_COLS];
static __device__ float g_xm  [BATCH*3*128];
static __device__ float g_xmp [BATCH*3*32*128];
static __device__ float g_bias[BATCH*3*512];
static __device__ __align__(16) __nv_bfloat16 g_Wh[W_TOT];
static __device__ __align__(16) __nv_bfloat16 g_Wl[W_TOT];

// ------------------------- helpers ------------------------------------------
__device__ __forceinline__ void lna3(float p0,float p1,float p2,
                                     float q0,float q1,float q2,
                                     float&o0,float&o1,float&o2)
{
    float dot = p0*q0 + p1*q1 + p2*q2;
    float dsq = q0*q0 + q1*q1 + q2*q2;
    float s = (dot < 0.f) ? 0.8f*dot/(dsq + 1e-6f) : 0.f;
    o0 = p0 - s*q0; o1 = p1 - s*q1; o2 = p2 - s*q2;
}

__device__ __forceinline__ void cvt2bf_hl(float x, float y, uint32_t& h, uint32_t& l)
{
    __nv_bfloat16 hx = __float2bfloat16(x), hy = __float2bfloat16(y);
    __nv_bfloat16 lx = __float2bfloat16(x - __bfloat162float(hx));
    __nv_bfloat16 ly = __float2bfloat16(y - __bfloat162float(hy));
    __nv_bfloat162 hp; hp.x = hx; hp.y = hy;
    __nv_bfloat162 lp; lp.x = lx; lp.y = ly;
    h = *(uint32_t*)&hp; l = *(uint32_t*)&lp;
}

// ------------------------- prep / KNN ----------------------------------------
__global__ void k_prep(const float* __restrict__ x)
{
    int i = blockIdx.x*blockDim.x + threadIdx.x;
    if (i >= BN_ALL) return;
    int b = i / NPTS, n = i - b*NPTS;
    float vx = x[(b*3+0)*NPTS + n];
    float vy = x[(b*3+1)*NPTS + n];
    float vz = x[(b*3+2)*NPTS + n];
    g_X0[i*3+0]=vx; g_X0[i*3+1]=vy; g_X0[i*3+2]=vz;
    float sq = fmaf(vz,vz, fmaf(vy,vy, vx*vx));
    float4 p; p.x=vx; p.y=vy; p.z=vz; p.w=sq;
    g_pts4[i] = p;
}

__global__ void k_knn_part()
{
    int t = blockIdx.x*blockDim.x + threadIdx.x;
    if (t >= BN_ALL*4) return;
    int bn    = t & (BN_ALL-1);
    int chunk = t >> 13;
    int b = bn / NPTS;
    float4 pv = g_pts4[bn];
    float px = pv.x, py = pv.y, pz = pv.z, sn = pv.w;
    const float4* Pb = g_pts4 + b*NPTS;

    float bd[KNN]; int bi[KNN];
    #pragma unroll
    for (int i = 0; i < KNN; i++){ bd[i] = 3.4e38f; bi[i] = 0; }
    float worst = 3.4e38f;
    int m0 = chunk*512;
    #pragma unroll 4
    for (int mm = 0; mm < 512; mm++){
        int m = m0 + mm;
        float4 c = Pb[m];
        float dot = fmaf(pz,c.z, fmaf(py,c.y, px*c.x));
        float d2  = (sn + c.w) - 2.f*dot;
        if (d2 < worst){
            int p = KNN-1;
            while (p > 0 && bd[p-1] > d2){ bd[p]=bd[p-1]; bi[p]=bi[p-1]; p--; }
            bd[p] = d2; bi[p] = m;
            worst = bd[KNN-1];
        }
    }
    float* od = g_knnd + bn*64 + chunk*16;
    int*   oi = g_knni + bn*64 + chunk*16;
    #pragma unroll
    for (int i = 0; i < 4; i++){
        float4 vd = { bd[i*4], bd[i*4+1], bd[i*4+2], bd[i*4+3] };
        int4   vi = { bi[i*4], bi[i*4+1], bi[i*4+2], bi[i*4+3] };
        *(float4*)(od + i*4) = vd;
        *(int4*)(oi + i*4)   = vi;
    }
}

// 4-way head-pointer merge (r14-proven; no dynamic local indexing)
__global__ void k_knn_merge()
{
    int bn = blockIdx.x*blockDim.x + threadIdx.x;
    if (bn >= BN_ALL) return;
    const float* cd = g_knnd + bn*64;
    const int*   ci = g_knni + bn*64;
    int h0 = 0, h1 = 0, h2 = 0, h3 = 0;
    float d0 = cd[0], d1 = cd[16], d2 = cd[32], d3 = cd[48];
    int* out = g_idx + bn*KNN;
    #pragma unroll
    for (int i = 0; i < KNN; i++){
        float best = d0; int sel = 0;
        if (d1 < best){ best = d1; sel = 1; }
        if (d2 < best){ best = d2; sel = 2; }
        if (d3 < best){ best = d3; sel = 3; }
        int idx;
        if      (sel == 0){ idx = ci[h0];      h0++; d0 = cd[h0]; }
        else if (sel == 1){ idx = ci[16 + h1]; h1++; d1 = cd[16 + h1]; }
        else if (sel == 2){ idx = ci[32 + h2]; h2++; d2 = cd[32 + h2]; }
        else              { idx = ci[48 + h3]; h3++; d3 = cd[48 + h3]; }
        out[i] = idx;
    }
}

// ------------------------- layer 1 direct Y build (C=1, O=16), vec4 ---------
__global__ void k_layer1(const float* __restrict__ w1f, const float* __restrict__ w1d)
{
    int t = blockIdx.x*blockDim.x + threadIdx.x;
    if (t >= BN_ALL*48) return;
    int bn = t / 48, r = t - bn*48;
    int pl = r >> 2, o4 = (r & 3)*4;
    int g = pl / 3, d = pl - g*3;
    float xv = g_X0[bn*3 + d];
    const float* W = (g < 2) ? w1f : w1d;
    float4 wa = *(const float4*)&W[o4*2];
    float4 wb = *(const float4*)&W[o4*2 + 4];
    float4 out;
    if ((g & 1) == 0){
        out.x = wa.x*xv; out.y = wa.z*xv; out.z = wb.x*xv; out.w = wb.z*xv;
    } else {
        out.x = (wa.y-wa.x)*xv; out.y = (wa.w-wa.z)*xv;
        out.z = (wb.y-wb.x)*xv; out.w = (wb.w-wb.z)*xv;
    }
    *(float4*)&g_Y[(size_t)bn*192 + pl*16 + o4] = out;
}

// ------------------------- ONE combined weight-combine kernel ---------------
__device__ __forceinline__ void split_store(size_t idx, float v)
{
    __nv_bfloat16 h = __float2bfloat16(v);
    g_Wh[idx] = h;
    g_Wl[idx] = __float2bfloat16(v - __bfloat162float(h));
}

__device__ __forceinline__ float graph_w(const float* Wf, const float* Wd,
                                         int C, int O, int local)
{
    int r = local / C, c = local - r*C;
    int g = r / O, o = r - g*O;
    if (g == 0) return Wf[o*2*C + c];
    if (g == 1) return Wf[o*2*C + C + c] - Wf[o*2*C + c];
    if (g == 2) return Wd[o*2*C + c];
    return Wd[o*2*C + C + c] - Wd[o*2*C + c];
}

__global__ void k_wcomb_all(const float* __restrict__ w2f, const float* __restrict__ w2d,
                            const float* __restrict__ w3f, const float* __restrict__ w3d,
                            const float* __restrict__ w4f, const float* __restrict__ w4d,
                            const float* __restrict__ wcf,
                            const float* __restrict__ wi1f, const float* __restrict__ wi1d,
                            const float* __restrict__ wi2f, const float* __restrict__ wi2d)
{
    int t = blockIdx.x*blockDim.x + threadIdx.x;
    if (t >= W_TOT) return;
    float v;
    if (t < WOF_L3)      v = graph_w(w2f, w2d, 16, 32,  t - WOF_L2);
    else if (t < WOF_L4) v = graph_w(w3f, w3d, 32, 64,  t - WOF_L3);
    else if (t < WOF_C)  v = graph_w(w4f, w4d, 64, 128, t - WOF_L4);
    else if (t < WOF_I1) v = wcf[t - WOF_C];
    else if (t < WOF_I2){
        int l = t - WOF_I1, r = l >> 7, c = l & 127;
        v = (r < 128) ? wi1f[r*256 + c] : wi1d[(r-128)*256 + c];
    } else {
        int l = t - WOF_I2, r = l >> 7, c = l & 127;
        v = (r < 256) ? wi2f[r*128 + c] : wi2d[(r-256)*128 + c];
    }
    split_store(t, v);
}

// ------------------------- warp-MMA GEMM: stage-once, double-buffered -------
// Each 32-wide k-chunk staged ONCE into 4 arrays (Ah,Al,Bh,Bl), each double-
// buffered; 3 split terms (Ah·Bh + Al·Bh + Ah·Bl) run over the staged chunk
// while the next chunk stages.  64KB dynamic smem.
#define SWZ(off) ((off) ^ (((off)>>3)&0x30))
#define HG_TILE  8192
#define HG_SMEM  (8*HG_TILE)   // 65536

__device__ __forceinline__ void ldsm_x4(uint32_t* a, uint32_t addr)
{
    asm volatile("ldmatrix.sync.aligned.m8n8.x4.shared.b16 {%0,%1,%2,%3}, [%4];"
        : "=r"(a[0]),"=r"(a[1]),"=r"(a[2]),"=r"(a[3]) : "r"(addr));
}
__device__ __forceinline__ void ldsm_x2(uint32_t* b, uint32_t addr)
{
    asm volatile("ldmatrix.sync.aligned.m8n8.x2.shared.b16 {%0,%1}, [%2];"
        : "=r"(b[0]),"=r"(b[1]) : "r"(addr));
}
__device__ __forceinline__ void mma16816(float* d, const uint32_t* a, const uint32_t* b)
{
    asm volatile("mma.sync.aligned.m16n8k16.row.col.f32.bf16.bf16.f32 "
        "{%0,%1,%2,%3}, {%4,%5,%6,%7}, {%8,%9}, {%0,%1,%2,%3};"
        : "+f"(d[0]),"+f"(d[1]),"+f"(d[2]),"+f"(d[3])
        : "r"(a[0]),"r"(a[1]),"r"(a[2]),"r"(a[3]),"r"(b[0]),"r"(b[1]));
}

__global__ void __launch_bounds__(256) k_hgemm(int xsel, int useBias, int wofs,
                                               int R, int C, int CS, int co,
                                               int G, int O)
{
    extern __shared__ __align__(16) char smem[];
    char* sAh = smem;
    char* sAl = smem + 2*HG_TILE;
    char* sBh = smem + 4*HG_TILE;
    char* sBl = smem + 6*HG_TILE;
    const float* __restrict__ X = (xsel==0) ? g_xcat240 : (xsel==1) ? g_xcat256 : g_t128;

    int tid  = threadIdx.x, lane = tid & 31, warp = tid >> 5;
    int m0   = blockIdx.x*128, r0 = blockIdx.y*128;
    int nch  = (C + 31) >> 5;
    int wr   = (warp >> 2)*64;
    int wm   = (warp & 3)*32;

    int srow = tid >> 1, shalf = tid & 1;

    float acc[4][4][4];
    #pragma unroll
    for (int i=0;i<4;i++)
        #pragma unroll
        for (int j=0;j<4;j++)
            #pragma unroll
            for (int k=0;k<4;k++) acc[i][j][k]=0.f;

    uint4 aH0,aH1,aL0,aL1, bH0,bH1,bL0,bL1;

    auto stage = [&](int cblk){
        bool valid = (cblk*32 + shalf*16) < C;
        const uint4 z = {0,0,0,0};
        if (valid){
            size_t woff = wofs + (size_t)(r0+srow)*C + cblk*32 + shalf*16;
            const uint4* ph = (const uint4*)&g_Wh[woff];
            const uint4* pl = (const uint4*)&g_Wl[woff];
            aH0 = ph[0]; aH1 = ph[1];
            aL0 = pl[0]; aL1 = pl[1];
            const float4* q = (const float4*)&X[(size_t)(m0+srow)*CS + co + cblk*32 + shalf*16];
            float4 f0=q[0], f1=q[1], f2=q[2], f3=q[3];
            cvt2bf_hl(f0.x,f0.y, bH0.x, bL0.x); cvt2bf_hl(f0.z,f0.w, bH0.y, bL0.y);
            cvt2bf_hl(f1.x,f1.y, bH0.z, bL0.z); cvt2bf_hl(f1.z,f1.w, bH0.w, bL0.w);
            cvt2bf_hl(f2.x,f2.y, bH1.x, bL1.x); cvt2bf_hl(f2.z,f2.w, bH1.y, bL1.y);
            cvt2bf_hl(f3.x,f3.y, bH1.z, bL1.z); cvt2bf_hl(f3.z,f3.w, bH1.w, bL1.w);
        } else { aH0=aH1=aL0=aL1=bH0=bH1=bL0=bL1=z; }
    };
    auto commit = [&](int buf){
        uint32_t o0 = buf*HG_TILE + SWZ((uint32_t)(srow*64 + (shalf*2  )*16));
        uint32_t o1 = buf*HG_TILE + SWZ((uint32_t)(srow*64 + (shalf*2+1)*16));
        *(uint4*)(sAh+o0) = aH0;  *(uint4*)(sAh+o1) = aH1;
        *(uint4*)(sAl+o0) = aL0;  *(uint4*)(sAl+o1) = aL1;
        *(uint4*)(sBh+o0) = bH0;  *(uint4*)(sBh+o1) = bH1;
        *(uint4*)(sBl+o0) = bL0;  *(uint4*)(sBl+o1) = bL1;
    };

    uint32_t baseAh = (uint32_t)__cvta_generic_to_shared(sAh);
    uint32_t baseAl = (uint32_t)__cvta_generic_to_shared(sAl);
    uint32_t baseBh = (uint32_t)__cvta_generic_to_shared(sBh);
    uint32_t baseBl = (uint32_t)__cvta_generic_to_shared(sBl);

    stage(0); commit(0); __syncthreads();

    for (int ch = 0; ch < nch; ch++){
        if (ch+1 < nch) stage(ch+1);
        uint32_t bofs = (uint32_t)((ch & 1)*HG_TILE);
        #pragma unroll
        for (int term = 0; term < 3; term++){
            uint32_t baseA = ((term == 1) ? baseAl : baseAh) + bofs;
            uint32_t baseB = ((term == 2) ? baseBl : baseBh) + bofs;
            #pragma unroll
            for (int ks = 0; ks < 32; ks += 16){
                uint32_t a[4][4], b[4][2];
                #pragma unroll
                for (int i = 0; i < 4; i++){
                    uint32_t off = (uint32_t)((wr + i*16 + (lane & 15))*64 + ks*2 + (lane >> 4)*16);
                    ldsm_x4(a[i], baseA + SWZ(off));
                }
                #pragma unroll
                for (int j = 0; j < 4; j++){
                    uint32_t off = (uint32_t)((wm + j*8 + (lane & 7))*64 + ks*2 + ((lane >> 3) & 1)*16);
                    ldsm_x2(b[j], baseB + SWZ(off));
                }
                #pragma unroll
                for (int i = 0; i < 4; i++)
                    #pragma unroll
                    for (int j = 0; j < 4; j++)
                        mma16816(acc[i][j], a[i], b[j]);
            }
        }
        if (ch+1 < nch) commit((ch+1) & 1);
        __syncthreads();
    }

    #pragma unroll
    for (int i = 0; i < 4; i++){
        #pragma unroll
        for (int rh = 0; rh < 2; rh++){
            int r = r0 + wr + i*16 + (lane >> 2) + rh*8;
            int g = r / O, o = r - g*O;
            #pragma unroll
            for (int j = 0; j < 4; j++){
                #pragma unroll
                for (int c = 0; c < 2; c++){
                    int m  = m0 + wm + j*8 + (lane & 3)*2 + c;
                    int bn = m / 3, d = m - bn*3;
                    float v = acc[i][j][rh*2 + c];
                    if (useBias) v += g_bias[((bn/NPTS)*3 + d)*R + r];
                    g_Y[(size_t)((bn*G + g)*3 + d)*O + o] = v;
                }
            }
        }
    }
}

// ------------------------- gather + vec-LNA + mean over K (float4) ----------
template<int O, int PPB>
__global__ void __launch_bounds__(256) k_gather(int co)
{
    __shared__ int sidx[PPB*KNN];
    int t  = threadIdx.x;
    int p0 = blockIdx.x * PPB;
    for (int i = t; i < PPB*KNN; i += 256) sidx[i] = g_idx[p0*KNN + i];
    __syncthreads();

    constexpr int TPP = O/4;
    int pl = t / TPP;
    int oc = (t - pl*TPP)*4;
    int bn = p0 + pl;
    int jbase = (bn / NPTS) * NPTS;

    const float* Z = g_Y + (size_t)bn*12*O + oc;
    float4 zp0 = *(const float4*)(Z + 3*O);
    float4 zp1 = *(const float4*)(Z + 4*O);
    float4 zp2 = *(const float4*)(Z + 5*O);
    float4 zq0 = *(const float4*)(Z + 9*O);
    float4 zq1 = *(const float4*)(Z + 10*O);
    float4 zq2 = *(const float4*)(Z + 11*O);
    float a0[4] = {0,0,0,0}, a1[4] = {0,0,0,0}, a2[4] = {0,0,0,0};

    #pragma unroll 4
    for (int k = 0; k < KNN; k++){
        int j = jbase + sidx[pl*KNN + k];
        const float* Yj = g_Y + (size_t)j*12*O + oc;
        float4 P0 = *(const float4*)(Yj + 0*O);
        float4 P1 = *(const float4*)(Yj + 1*O);
        float4 P2 = *(const float4*)(Yj + 2*O);
        float4 Q0 = *(const float4*)(Yj + 6*O);
        float4 Q1 = *(const float4*)(Yj + 7*O);
        float4 Q2 = *(const float4*)(Yj + 8*O);
        #pragma unroll
        for (int c = 0; c < 4; c++){
            float p0v = (&P0.x)[c] + (&zp0.x)[c];
            float p1v = (&P1.x)[c] + (&zp1.x)[c];
            float p2v = (&P2.x)[c] + (&zp2.x)[c];
            float q0  = (&Q0.x)[c] + (&zq0.x)[c];
            float q1  = (&Q1.x)[c] + (&zq1.x)[c];
            float q2  = (&Q2.x)[c] + (&zq2.x)[c];
            float dot = p0v*q0 + p1v*q1 + p2v*q2;
            float dsq = q0*q0 + q1*q1 + q2*q2;
            float s = (dot < 0.f) ? 0.8f*dot/(dsq + 1e-6f) : 0.f;
            a0[c] += p0v - s*q0; a1[c] += p1v - s*q1; a2[c] += p2v - s*q2;
        }
    }
    float* out = g_xcat240 + (size_t)bn*3*240 + co + oc;
    float4 v0 = {a0[0]*0.0625f, a0[1]*0.0625f, a0[2]*0.0625f, a0[3]*0.0625f};
    float4 v1 = {a1[0]*0.0625f, a1[1]*0.0625f, a1[2]*0.0625f, a1[3]*0.0625f};
    float4 v2 = {a2[0]*0.0625f, a2[1]*0.0625f, a2[2]*0.0625f, a2[3]*0.0625f};
    *(float4*)(out)       = v0;
    *(float4*)(out + 240) = v1;
    *(float4*)(out + 480) = v2;
}

// ------------------------- layer c: dc GEMV (1x240), vec4 --------------------
__global__ void k_dc(const float* __restrict__ wcd)
{
    int gt = blockIdx.x*blockDim.x + threadIdx.x;
    int warp = gt >> 5, lane = gt & 31;
    if (warp >= M_COLS) return;
    const float* row = g_xcat240 + (size_t)warp*240;
    float s = 0.f;
    for (int c = lane; c < 60; c += 32){
        float4 a = *(const float4*)&row[c*4];
        float4 w = *(const float4*)&wcd[c*4];
        s += a.x*w.x + a.y*w.y + a.z*w.z + a.w*w.w;
    }
    #pragma unroll
    for (int off = 16; off; off >>= 1) s += __shfl_xor_sync(0xffffffffu, s, off);
    if (lane == 0) g_dc[warp] = s;
}

// layer c LNA (q shared across o), vec4
__global__ void k_lna_c()
{
    int t = blockIdx.x*blockDim.x + threadIdx.x;
    if (t >= BN_ALL*32) return;
    int bn = t >> 5, oc = (t & 31)*4;
    const float* Yb = g_Y + (size_t)bn*384 + oc;
    float4 P0 = *(const float4*)(Yb);
    float4 P1 = *(const float4*)(Yb + 128);
    float4 P2 = *(const float4*)(Yb + 256);
    float q0 = g_dc[bn*3+0], q1 = g_dc[bn*3+1], q2 = g_dc[bn*3+2];
    float4 O0, O1, O2;
    #pragma unroll
    for (int c = 0; c < 4; c++){
        float o0,o1,o2;
        lna3((&P0.x)[c], (&P1.x)[c], (&P2.x)[c], q0, q1, q2, o0,o1,o2);
        (&O0.x)[c]=o0; (&O1.x)[c]=o1; (&O2.x)[c]=o2;
    }
    float* out = g_xcat256 + (size_t)bn*3*256 + oc;
    *(float4*)(out)       = O0;
    *(float4*)(out + 256) = O1;
    *(float4*)(out + 512) = O2;
}

// ------------------------- xm mean -------------------------------------------
__global__ void k_xm_part()
{
    int blk  = blockIdx.x;
    int slab = blk & 31;
    int bd3  = blk >> 5;
    int b = bd3 / 3, d = bd3 - b*3;
    int o = threadIdx.x;
    float s = 0.f;
    for (int nn = 0; nn < 64; nn++){
        int n = slab*64 + nn;
        s += g_xcat256[((size_t)(b*NPTS+n)*3 + d)*256 + o];
    }
    g_xmp[(size_t)(bd3*32 + slab)*128 + o] = s;
}

__global__ void k_xm_final()
{
    int t = blockIdx.x*blockDim.x + threadIdx.x;
    if (t >= BATCH*3*128) return;
    int bd3 = t >> 7, o = t & 127;
    float s = 0.f;
    for (int sl = 0; sl < 32; sl++) s += g_xmp[(size_t)(bd3*32+sl)*128 + o];
    g_xm[bd3*128 + o] = s * (1.f/2048.f);
}

__global__ void k_bias_i1(const float* __restrict__ wi1f, const float* __restrict__ wi1d)
{
    int t = blockIdx.x*blockDim.x + threadIdx.x;
    if (t >= BATCH*3*256) return;
    int bd3 = t >> 8, r = t & 255;
    const float* wrow = (r < 128) ? (wi1f + r*256) : (wi1d + (r-128)*256);
    float s = 0.f;
    for (int c = 0; c < 128; c++) s = fmaf(wrow[128+c], g_xm[bd3*128 + c], s);
    g_bias[bd3*256 + r] = s;
}

// ------------------------- i1 LNA (writes t128 only) ------------------------
__global__ void k_lna_pd()
{
    int t = blockIdx.x*blockDim.x + threadIdx.x;
    if (t >= BN_ALL*32) return;
    int bn = t >> 5, oc = (t & 31)*4;
    const float* Yb = g_Y + (size_t)bn*768 + oc;
    float4 P0 = *(const float4*)(Yb + 0*128);
    float4 P1 = *(const float4*)(Yb + 1*128);
    float4 P2 = *(const float4*)(Yb + 2*128);
    float4 Q0 = *(const float4*)(Yb + 3*128);
    float4 Q1 = *(const float4*)(Yb + 4*128);
    float4 Q2 = *(const float4*)(Yb + 5*128);
    float4 O0, O1, O2;
    #pragma unroll
    for (int c = 0; c < 4; c++){
        float o0,o1,o2;
        lna3((&P0.x)[c], (&P1.x)[c], (&P2.x)[c],
             (&Q0.x)[c], (&Q1.x)[c], (&Q2.x)[c], o0,o1,o2);
        (&O0.x)[c]=o0; (&O1.x)[c]=o1; (&O2.x)[c]=o2;
    }
    float* out = g_t128 + (size_t)bn*3*128 + oc;
    *(float4*)(out)=O0; *(float4*)(out+128)=O1; *(float4*)(out+256)=O2;
}

// ------------------------- final invariant (fused i2-LNA + dot) --------------
__global__ void __launch_bounds__(256) k_inv(float* __restrict__ out)
{
    __shared__ float tile[256*33];
    int n0 = blockIdx.x * 32;
    int b  = n0 / NPTS;
    int t  = threadIdx.x;
    int pg = t >> 6;             // 0..3 -> 8 points each
    int oc = (t & 63)*4;         // 4 o-channels
    bool hi = (oc >= 128);
    float4 a0c, a1c, a2c;
    if (hi){
        a0c = *(const float4*)&g_xm[(b*3+0)*128 + oc - 128];
        a1c = *(const float4*)&g_xm[(b*3+1)*128 + oc - 128];
        a2c = *(const float4*)&g_xm[(b*3+2)*128 + oc - 128];
    }
    for (int pp = 0; pp < 8; pp++){
        int p = pg*8 + pp;
        int bn = n0 + p;
        size_t base = (size_t)bn*3*256 + oc;
        float4 a0, a1, a2;
        if (hi){ a0 = a0c; a1 = a1c; a2 = a2c; }
        else {
            a0 = *(const float4*)&g_xcat256[base];
            a1 = *(const float4*)&g_xcat256[base + 256];
            a2 = *(const float4*)&g_xcat256[base + 512];
        }
        const float* Yb = g_Y + (size_t)bn*1536 + oc;
        float4 P0 = *(const float4*)(Yb + 0*256);
        float4 P1 = *(const float4*)(Yb + 1*256);
        float4 P2 = *(const float4*)(Yb + 2*256);
        float4 Q0 = *(const float4*)(Yb + 3*256);
        float4 Q1 = *(const float4*)(Yb + 4*256);
        float4 Q2 = *(const float4*)(Yb + 5*256);
        #pragma unroll
        for (int c = 0; c < 4; c++){
            float o0,o1,o2;
            lna3((&P0.x)[c], (&P1.x)[c], (&P2.x)[c],
                 (&Q0.x)[c], (&Q1.x)[c], (&Q2.x)[c], o0,o1,o2);
            float s = (&a0.x)[c]*o0 + (&a1.x)[c]*o1 + (&a2.x)[c]*o2;
            tile[(oc + c)*33 + p] = s;
        }
    }
    __syncthreads();
    int nn0 = n0 - b*NPTS;
    int p   = t & 31, og = t >> 5;
    for (int o = og; o < 256; o += 8)
        out[(size_t)(b*256 + o)*NPTS + nn0 + p] = tile[o*33 + p];
}

// ------------------------- launcher -----------------------------------------
extern "C" void kernel_launch(void* const* d_in, const int* in_sizes, int n_in,
                              void* d_out, int out_size)
{
    const float* x    = (const float*)d_in[0];
    const float* w1f  = (const float*)d_in[1];
    const float* w1d  = (const float*)d_in[2];
    const float* w2f  = (const float*)d_in[3];
    const float* w2d  = (const float*)d_in[4];
    const float* w3f  = (const float*)d_in[5];
    const float* w3d  = (const float*)d_in[6];
    const float* w4f  = (const float*)d_in[7];
    const float* w4d  = (const float*)d_in[8];
    const float* wcf  = (const float*)d_in[9];
    const float* wcd  = (const float*)d_in[10];
    const float* wi1f = (const float*)d_in[11];
    const float* wi1d = (const float*)d_in[12];
    const float* wi2f = (const float*)d_in[13];
    const float* wi2d = (const float*)d_in[14];
    float* out = (float*)d_out;

    cudaFuncSetAttribute(k_hgemm, cudaFuncAttributeMaxDynamicSharedMemorySize, HG_SMEM);

    // all weight prep in one launch, up front
    k_wcomb_all<<<(W_TOT+255)/256, 256>>>(w2f, w2d, w3f, w3d, w4f, w4d,
                                          wcf, wi1f, wi1d, wi2f, wi2d);

    k_prep<<<(BN_ALL+127)/128, 128>>>(x);
    k_knn_part<<<(BN_ALL*4+127)/128, 128>>>();
    k_knn_merge<<<(BN_ALL+127)/128, 128>>>();

    // ---- layer 1 (C=1 -> O=16)
    k_layer1<<<(BN_ALL*48+255)/256, 256>>>(w1f, w1d);
    k_gather<16,64><<<BN_ALL/64, 256>>>(0);

    // ---- layer 2 (C=16 -> O=32)
    k_hgemm<<<dim3(M_COLS/128, 1), 256, HG_SMEM>>>(0, 0, WOF_L2, 128, 16, 240, 0, 4, 32);
    k_gather<32,32><<<BN_ALL/32, 256>>>(16);

    // ---- layer 3 (C=32 -> O=64)
    k_hgemm<<<dim3(M_COLS/128, 2), 256, HG_SMEM>>>(0, 0, WOF_L3, 256, 32, 240, 16, 4, 64);
    k_gather<64,16><<<BN_ALL/16, 256>>>(48);

    // ---- layer 4 (C=64 -> O=128)
    k_hgemm<<<dim3(M_COLS/128, 4), 256, HG_SMEM>>>(0, 0, WOF_L4, 512, 64, 240, 48, 4, 128);
    k_gather<128,8><<<BN_ALL/8, 256>>>(112);

    // ---- concat layer (wcf 128x240, wcd 1x240)
    k_hgemm<<<dim3(M_COLS/128, 1), 256, HG_SMEM>>>(0, 0, WOF_C, 128, 240, 240, 0, 1, 128);
    k_dc<<<(M_COLS*32+255)/256, 256>>>(wcd);
    k_lna_c<<<(BN_ALL*32+255)/256, 256>>>();

    // ---- xm mean over N
    k_xm_part<<<BATCH*3*32, 128>>>();
    k_xm_final<<<(BATCH*3*128+255)/256, 256>>>();

    // ---- i1 (wi1f/wi1d 128x256; contract 128 + xm bias)
    k_bias_i1<<<(BATCH*3*256+255)/256, 256>>>(wi1f, wi1d);
    k_hgemm<<<dim3(M_COLS/128, 2), 256, HG_SMEM>>>(1, 1, WOF_I1, 256, 128, 256, 0, 2, 128);
    k_lna_pd<<<(BN_ALL*32+255)/256, 256>>>();

    // ---- i2 (wi2f/wi2d 256x128) -> LNA fused into k_inv
    k_hgemm<<<dim3(M_COLS/128, 4), 256, HG_SMEM>>>(2, 0, WOF_I2, 512, 128, 128, 0, 2, 256);

    // ---- invariant output (B,256,N)
    k_inv<<<BN_ALL/32, 256>>>(out);
}

// round 16
// speedup vs baseline: 1.0996x; 1.0218x over previous
#include <cuda_runtime.h>
#include <cuda_bf16.h>
#include <cstdint>

#define BATCH 4
#define NPTS  2048
#define KNN   16
#define BN_ALL (BATCH*NPTS)      // 8192
#define M_COLS (BN_ALL*3)        // 24576

// weight buffer offsets (elements)
#define WOF_L2 0
#define WOF_L3 2048
#define WOF_L4 10240
#define WOF_C  43008
#define WOF_I1 73728
#define WOF_I2 106496
#define W_TOT  172032

// ------------------------- scratch (device globals; no mallocs) -------------
static __device__ __align__(16) float g_X0[BN_ALL*3];
static __device__ __align__(16) float4 g_pts4[BN_ALL];   // (x,y,z,|x|^2)
static __device__ int   g_idx[BN_ALL*KNN];
static __device__ __align__(16) float g_knnd[BN_ALL*64];
static __device__ __align__(16) int   g_knni[BN_ALL*64];
static __device__ __align__(16) float g_xcat240[BN_ALL*3*240];
static __device__ __align__(16) float g_xcat256[BN_ALL*3*256];
static __device__ __align__(16) float g_t128 [BN_ALL*3*128];
static __device__ __align__(16) float g_Y    [BN_ALL*1536];   // reused per layer
static __device__ float g_dc  [M_COLS];
static __device__ float g_xm  [BATCH*3*128];
static __device__ float g_xmp [BATCH*3*32*128];
static __device__ float g_bias[BATCH*3*512];
static __device__ __align__(16) __nv_bfloat16 g_Wh[W_TOT];
static __device__ __align__(16) __nv_bfloat16 g_Wl[W_TOT];

// ------------------------- helpers ------------------------------------------
__device__ __forceinline__ void lna3(float p0,float p1,float p2,
                                     float q0,float q1,float q2,
                                     float&o0,float&o1,float&o2)
{
    float dot = p0*q0 + p1*q1 + p2*q2;
    float dsq = q0*q0 + q1*q1 + q2*q2;
    float s = (dot < 0.f) ? 0.8f*dot/(dsq + 1e-6f) : 0.f;
    o0 = p0 - s*q0; o1 = p1 - s*q1; o2 = p2 - s*q2;
}

__device__ __forceinline__ void cvt2bf_hl(float x, float y, uint32_t& h, uint32_t& l)
{
    __nv_bfloat16 hx = __float2bfloat16(x), hy = __float2bfloat16(y);
    __nv_bfloat16 lx = __float2bfloat16(x - __bfloat162float(hx));
    __nv_bfloat16 ly = __float2bfloat16(y - __bfloat162float(hy));
    __nv_bfloat162 hp; hp.x = hx; hp.y = hy;
    __nv_bfloat162 lp; lp.x = lx; lp.y = ly;
    h = *(uint32_t*)&hp; l = *(uint32_t*)&lp;
}

// ------------------------- prep / KNN ----------------------------------------
__global__ void k_prep(const float* __restrict__ x)
{
    int i = blockIdx.x*blockDim.x + threadIdx.x;
    if (i >= BN_ALL) return;
    int b = i / NPTS, n = i - b*NPTS;
    float vx = x[(b*3+0)*NPTS + n];
    float vy = x[(b*3+1)*NPTS + n];
    float vz = x[(b*3+2)*NPTS + n];
    g_X0[i*3+0]=vx; g_X0[i*3+1]=vy; g_X0[i*3+2]=vz;
    float sq = fmaf(vz,vz, fmaf(vy,vy, vx*vx));
    float4 p; p.x=vx; p.y=vy; p.z=vz; p.w=sq;
    g_pts4[i] = p;
}

// smem-staged scan: every 128-thread block lies within ONE batch and ONE
// chunk, and all threads scan the same 512 candidates (8KB) -> stage once.
__global__ void __launch_bounds__(128) k_knn_part()
{
    __shared__ __align__(16) float4 spts[512];
    int tid = threadIdx.x;
    int t   = blockIdx.x*128 + tid;
    int bn    = t & (BN_ALL-1);
    int chunk = t >> 13;
    int b  = bn / NPTS;
    int m0 = chunk*512;
    const float4* Pb = g_pts4 + b*NPTS;
    #pragma unroll
    for (int i = 0; i < 4; i++)
        spts[tid + i*128] = Pb[m0 + tid + i*128];
    __syncthreads();

    float4 pv = g_pts4[bn];
    float px = pv.x, py = pv.y, pz = pv.z, sn = pv.w;

    float bd[KNN]; int bi[KNN];
    #pragma unroll
    for (int i = 0; i < KNN; i++){ bd[i] = 3.4e38f; bi[i] = 0; }
    float worst = 3.4e38f;
    #pragma unroll 4
    for (int mm = 0; mm < 512; mm++){
        float4 c = spts[mm];
        float dot = fmaf(pz,c.z, fmaf(py,c.y, px*c.x));
        float d2  = (sn + c.w) - 2.f*dot;
        if (d2 < worst){
            int p = KNN-1;
            while (p > 0 && bd[p-1] > d2){ bd[p]=bd[p-1]; bi[p]=bi[p-1]; p--; }
            bd[p] = d2; bi[p] = m0 + mm;
            worst = bd[KNN-1];
        }
    }
    float* od = g_knnd + bn*64 + chunk*16;
    int*   oi = g_knni + bn*64 + chunk*16;
    #pragma unroll
    for (int i = 0; i < 4; i++){
        float4 vd = { bd[i*4], bd[i*4+1], bd[i*4+2], bd[i*4+3] };
        int4   vi = { bi[i*4], bi[i*4+1], bi[i*4+2], bi[i*4+3] };
        *(float4*)(od + i*4) = vd;
        *(int4*)(oi + i*4)   = vi;
    }
}

// 4-way head-pointer merge (r14-proven; no dynamic local indexing)
__global__ void k_knn_merge()
{
    int bn = blockIdx.x*blockDim.x + threadIdx.x;
    if (bn >= BN_ALL) return;
    const float* cd = g_knnd + bn*64;
    const int*   ci = g_knni + bn*64;
    int h0 = 0, h1 = 0, h2 = 0, h3 = 0;
    float d0 = cd[0], d1 = cd[16], d2 = cd[32], d3 = cd[48];
    int* out = g_idx + bn*KNN;
    #pragma unroll
    for (int i = 0; i < KNN; i++){
        float best = d0; int sel = 0;
        if (d1 < best){ best = d1; sel = 1; }
        if (d2 < best){ best = d2; sel = 2; }
        if (d3 < best){ best = d3; sel = 3; }
        int idx;
        if      (sel == 0){ idx = ci[h0];      h0++; d0 = cd[h0]; }
        else if (sel == 1){ idx = ci[16 + h1]; h1++; d1 = cd[16 + h1]; }
        else if (sel == 2){ idx = ci[32 + h2]; h2++; d2 = cd[32 + h2]; }
        else              { idx = ci[48 + h3]; h3++; d3 = cd[48 + h3]; }
        out[i] = idx;
    }
}

// ------------------------- layer 1 direct Y build (C=1, O=16), vec4 ---------
__global__ void k_layer1(const float* __restrict__ w1f, const float* __restrict__ w1d)
{
    int t = blockIdx.x*blockDim.x + threadIdx.x;
    if (t >= BN_ALL*48) return;
    int bn = t / 48, r = t - bn*48;
    int pl = r >> 2, o4 = (r & 3)*4;
    int g = pl / 3, d = pl - g*3;
    float xv = g_X0[bn*3 + d];
    const float* W = (g < 2) ? w1f : w1d;
    float4 wa = *(const float4*)&W[o4*2];
    float4 wb = *(const float4*)&W[o4*2 + 4];
    float4 out;
    if ((g & 1) == 0){
        out.x = wa.x*xv; out.y = wa.z*xv; out.z = wb.x*xv; out.w = wb.z*xv;
    } else {
        out.x = (wa.y-wa.x)*xv; out.y = (wa.w-wa.z)*xv;
        out.z = (wb.y-wb.x)*xv; out.w = (wb.w-wb.z)*xv;
    }
    *(float4*)&g_Y[(size_t)bn*192 + pl*16 + o4] = out;
}

// ------------------------- ONE combined weight-combine kernel ---------------
__device__ __forceinline__ void split_store(size_t idx, float v)
{
    __nv_bfloat16 h = __float2bfloat16(v);
    g_Wh[idx] = h;
    g_Wl[idx] = __float2bfloat16(v - __bfloat162float(h));
}

__device__ __forceinline__ float graph_w(const float* Wf, const float* Wd,
                                         int C, int O, int local)
{
    int r = local / C, c = local - r*C;
    int g = r / O, o = r - g*O;
    if (g == 0) return Wf[o*2*C + c];
    if (g == 1) return Wf[o*2*C + C + c] - Wf[o*2*C + c];
    if (g == 2) return Wd[o*2*C + c];
    return Wd[o*2*C + C + c] - Wd[o*2*C + c];
}

__global__ void k_wcomb_all(const float* __restrict__ w2f, const float* __restrict__ w2d,
                            const float* __restrict__ w3f, const float* __restrict__ w3d,
                            const float* __restrict__ w4f, const float* __restrict__ w4d,
                            const float* __restrict__ wcf,
                            const float* __restrict__ wi1f, const float* __restrict__ wi1d,
                            const float* __restrict__ wi2f, const float* __restrict__ wi2d)
{
    int t = blockIdx.x*blockDim.x + threadIdx.x;
    if (t >= W_TOT) return;
    float v;
    if (t < WOF_L3)      v = graph_w(w2f, w2d, 16, 32,  t - WOF_L2);
    else if (t < WOF_L4) v = graph_w(w3f, w3d, 32, 64,  t - WOF_L3);
    else if (t < WOF_C)  v = graph_w(w4f, w4d, 64, 128, t - WOF_L4);
    else if (t < WOF_I1) v = wcf[t - WOF_C];
    else if (t < WOF_I2){
        int l = t - WOF_I1, r = l >> 7, c = l & 127;
        v = (r < 128) ? wi1f[r*256 + c] : wi1d[(r-128)*256 + c];
    } else {
        int l = t - WOF_I2, r = l >> 7, c = l & 127;
        v = (r < 256) ? wi2f[r*128 + c] : wi2d[(r-256)*128 + c];
    }
    split_store(t, v);
}

// ------------------------- warp-MMA GEMM: stage-once, double-buffered -------
#define SWZ(off) ((off) ^ (((off)>>3)&0x30))
#define HG_TILE  8192
#define HG_SMEM  (8*HG_TILE)   // 65536

__device__ __forceinline__ void ldsm_x4(uint32_t* a, uint32_t addr)
{
    asm volatile("ldmatrix.sync.aligned.m8n8.x4.shared.b16 {%0,%1,%2,%3}, [%4];"
        : "=r"(a[0]),"=r"(a[1]),"=r"(a[2]),"=r"(a[3]) : "r"(addr));
}
__device__ __forceinline__ void ldsm_x2(uint32_t* b, uint32_t addr)
{
    asm volatile("ldmatrix.sync.aligned.m8n8.x2.shared.b16 {%0,%1}, [%2];"
        : "=r"(b[0]),"=r"(b[1]) : "r"(addr));
}
__device__ __forceinline__ void mma16816(float* d, const uint32_t* a, const uint32_t* b)
{
    asm volatile("mma.sync.aligned.m16n8k16.row.col.f32.bf16.bf16.f32 "
        "{%0,%1,%2,%3}, {%4,%5,%6,%7}, {%8,%9}, {%0,%1,%2,%3};"
        : "+f"(d[0]),"+f"(d[1]),"+f"(d[2]),"+f"(d[3])
        : "r"(a[0]),"r"(a[1]),"r"(a[2]),"r"(a[3]),"r"(b[0]),"r"(b[1]));
}

__global__ void __launch_bounds__(256) k_hgemm(int xsel, int useBias, int wofs,
                                               int R, int C, int CS, int co,
                                               int G, int O)
{
    extern __shared__ __align__(16) char smem[];
    char* sAh = smem;
    char* sAl = smem + 2*HG_TILE;
    char* sBh = smem + 4*HG_TILE;
    char* sBl = smem + 6*HG_TILE;
    const float* __restrict__ X = (xsel==0) ? g_xcat240 : (xsel==1) ? g_xcat256 : g_t128;

    int tid  = threadIdx.x, lane = tid & 31, warp = tid >> 5;
    int m0   = blockIdx.x*128, r0 = blockIdx.y*128;
    int nch  = (C + 31) >> 5;
    int wr   = (warp >> 2)*64;
    int wm   = (warp & 3)*32;

    int srow = tid >> 1, shalf = tid & 1;

    float acc[4][4][4];
    #pragma unroll
    for (int i=0;i<4;i++)
        #pragma unroll
        for (int j=0;j<4;j++)
            #pragma unroll
            for (int k=0;k<4;k++) acc[i][j][k]=0.f;

    uint4 aH0,aH1,aL0,aL1, bH0,bH1,bL0,bL1;

    auto stage = [&](int cblk){
        bool valid = (cblk*32 + shalf*16) < C;
        const uint4 z = {0,0,0,0};
        if (valid){
            size_t woff = wofs + (size_t)(r0+srow)*C + cblk*32 + shalf*16;
            const uint4* ph = (const uint4*)&g_Wh[woff];
            const uint4* pl = (const uint4*)&g_Wl[woff];
            aH0 = ph[0]; aH1 = ph[1];
            aL0 = pl[0]; aL1 = pl[1];
            const float4* q = (const float4*)&X[(size_t)(m0+srow)*CS + co + cblk*32 + shalf*16];
            float4 f0=q[0], f1=q[1], f2=q[2], f3=q[3];
            cvt2bf_hl(f0.x,f0.y, bH0.x, bL0.x); cvt2bf_hl(f0.z,f0.w, bH0.y, bL0.y);
            cvt2bf_hl(f1.x,f1.y, bH0.z, bL0.z); cvt2bf_hl(f1.z,f1.w, bH0.w, bL0.w);
            cvt2bf_hl(f2.x,f2.y, bH1.x, bL1.x); cvt2bf_hl(f2.z,f2.w, bH1.y, bL1.y);
            cvt2bf_hl(f3.x,f3.y, bH1.z, bL1.z); cvt2bf_hl(f3.z,f3.w, bH1.w, bL1.w);
        } else { aH0=aH1=aL0=aL1=bH0=bH1=bL0=bL1=z; }
    };
    auto commit = [&](int buf){
        uint32_t o0 = buf*HG_TILE + SWZ((uint32_t)(srow*64 + (shalf*2  )*16));
        uint32_t o1 = buf*HG_TILE + SWZ((uint32_t)(srow*64 + (shalf*2+1)*16));
        *(uint4*)(sAh+o0) = aH0;  *(uint4*)(sAh+o1) = aH1;
        *(uint4*)(sAl+o0) = aL0;  *(uint4*)(sAl+o1) = aL1;
        *(uint4*)(sBh+o0) = bH0;  *(uint4*)(sBh+o1) = bH1;
        *(uint4*)(sBl+o0) = bL0;  *(uint4*)(sBl+o1) = bL1;
    };

    uint32_t baseAh = (uint32_t)__cvta_generic_to_shared(sAh);
    uint32_t baseAl = (uint32_t)__cvta_generic_to_shared(sAl);
    uint32_t baseBh = (uint32_t)__cvta_generic_to_shared(sBh);
    uint32_t baseBl = (uint32_t)__cvta_generic_to_shared(sBl);

    stage(0); commit(0); __syncthreads();

    for (int ch = 0; ch < nch; ch++){
        if (ch+1 < nch) stage(ch+1);
        uint32_t bofs = (uint32_t)((ch & 1)*HG_TILE);
        #pragma unroll
        for (int term = 0; term < 3; term++){
            uint32_t baseA = ((term == 1) ? baseAl : baseAh) + bofs;
            uint32_t baseB = ((term == 2) ? baseBl : baseBh) + bofs;
            #pragma unroll
            for (int ks = 0; ks < 32; ks += 16){
                uint32_t a[4][4], b[4][2];
                #pragma unroll
                for (int i = 0; i < 4; i++){
                    uint32_t off = (uint32_t)((wr + i*16 + (lane & 15))*64 + ks*2 + (lane >> 4)*16);
                    ldsm_x4(a[i], baseA + SWZ(off));
                }
                #pragma unroll
                for (int j = 0; j < 4; j++){
                    uint32_t off = (uint32_t)((wm + j*8 + (lane & 7))*64 + ks*2 + ((lane >> 3) & 1)*16);
                    ldsm_x2(b[j], baseB + SWZ(off));
                }
                #pragma unroll
                for (int i = 0; i < 4; i++)
                    #pragma unroll
                    for (int j = 0; j < 4; j++)
                        mma16816(acc[i][j], a[i], b[j]);
            }
        }
        if (ch+1 < nch) commit((ch+1) & 1);
        __syncthreads();
    }

    #pragma unroll
    for (int i = 0; i < 4; i++){
        #pragma unroll
        for (int rh = 0; rh < 2; rh++){
            int r = r0 + wr + i*16 + (lane >> 2) + rh*8;
            int g = r / O, o = r - g*O;
            #pragma unroll
            for (int j = 0; j < 4; j++){
                #pragma unroll
                for (int c = 0; c < 2; c++){
                    int m  = m0 + wm + j*8 + (lane & 3)*2 + c;
                    int bn = m / 3, d = m - bn*3;
                    float v = acc[i][j][rh*2 + c];
                    if (useBias) v += g_bias[((bn/NPTS)*3 + d)*R + r];
                    g_Y[(size_t)((bn*G + g)*3 + d)*O + o] = v;
                }
            }
        }
    }
}

// ------------------------- gather + vec-LNA + mean over K (float4) ----------
template<int O, int PPB>
__global__ void __launch_bounds__(256) k_gather(int co)
{
    __shared__ int sidx[PPB*KNN];
    int t  = threadIdx.x;
    int p0 = blockIdx.x * PPB;
    for (int i = t; i < PPB*KNN; i += 256) sidx[i] = g_idx[p0*KNN + i];
    __syncthreads();

    constexpr int TPP = O/4;
    int pl = t / TPP;
    int oc = (t - pl*TPP)*4;
    int bn = p0 + pl;
    int jbase = (bn / NPTS) * NPTS;

    const float* Z = g_Y + (size_t)bn*12*O + oc;
    float4 zp0 = *(const float4*)(Z + 3*O);
    float4 zp1 = *(const float4*)(Z + 4*O);
    float4 zp2 = *(const float4*)(Z + 5*O);
    float4 zq0 = *(const float4*)(Z + 9*O);
    float4 zq1 = *(const float4*)(Z + 10*O);
    float4 zq2 = *(const float4*)(Z + 11*O);
    float a0[4] = {0,0,0,0}, a1[4] = {0,0,0,0}, a2[4] = {0,0,0,0};

    #pragma unroll 4
    for (int k = 0; k < KNN; k++){
        int j = jbase + sidx[pl*KNN + k];
        const float* Yj = g_Y + (size_t)j*12*O + oc;
        float4 P0 = *(const float4*)(Yj + 0*O);
        float4 P1 = *(const float4*)(Yj + 1*O);
        float4 P2 = *(const float4*)(Yj + 2*O);
        float4 Q0 = *(const float4*)(Yj + 6*O);
        float4 Q1 = *(const float4*)(Yj + 7*O);
        float4 Q2 = *(const float4*)(Yj + 8*O);
        #pragma unroll
        for (int c = 0; c < 4; c++){
            float p0v = (&P0.x)[c] + (&zp0.x)[c];
            float p1v = (&P1.x)[c] + (&zp1.x)[c];
            float p2v = (&P2.x)[c] + (&zp2.x)[c];
            float q0  = (&Q0.x)[c] + (&zq0.x)[c];
            float q1  = (&Q1.x)[c] + (&zq1.x)[c];
            float q2  = (&Q2.x)[c] + (&zq2.x)[c];
            float dot = p0v*q0 + p1v*q1 + p2v*q2;
            float dsq = q0*q0 + q1*q1 + q2*q2;
            float s = (dot < 0.f) ? 0.8f*dot/(dsq + 1e-6f) : 0.f;
            a0[c] += p0v - s*q0; a1[c] += p1v - s*q1; a2[c] += p2v - s*q2;
        }
    }
    float* out = g_xcat240 + (size_t)bn*3*240 + co + oc;
    float4 v0 = {a0[0]*0.0625f, a0[1]*0.0625f, a0[2]*0.0625f, a0[3]*0.0625f};
    float4 v1 = {a1[0]*0.0625f, a1[1]*0.0625f, a1[2]*0.0625f, a1[3]*0.0625f};
    float4 v2 = {a2[0]*0.0625f, a2[1]*0.0625f, a2[2]*0.0625f, a2[3]*0.0625f};
    *(float4*)(out)       = v0;
    *(float4*)(out + 240) = v1;
    *(float4*)(out + 480) = v2;
}

// ------------------------- layer c: dc GEMV (1x240), vec4 --------------------
__global__ void k_dc(const float* __restrict__ wcd)
{
    int gt = blockIdx.x*blockDim.x + threadIdx.x;
    int warp = gt >> 5, lane = gt & 31;
    if (warp >= M_COLS) return;
    const float* row = g_xcat240 + (size_t)warp*240;
    float s = 0.f;
    for (int c = lane; c < 60; c += 32){
        float4 a = *(const float4*)&row[c*4];
        float4 w = *(const float4*)&wcd[c*4];
        s += a.x*w.x + a.y*w.y + a.z*w.z + a.w*w.w;
    }
    #pragma unroll
    for (int off = 16; off; off >>= 1) s += __shfl_xor_sync(0xffffffffu, s, off);
    if (lane == 0) g_dc[warp] = s;
}

// layer c LNA (q shared across o), vec4
__global__ void k_lna_c()
{
    int t = blockIdx.x*blockDim.x + threadIdx.x;
    if (t >= BN_ALL*32) return;
    int bn = t >> 5, oc = (t & 31)*4;
    const float* Yb = g_Y + (size_t)bn*384 + oc;
    float4 P0 = *(const float4*)(Yb);
    float4 P1 = *(const float4*)(Yb + 128);
    float4 P2 = *(const float4*)(Yb + 256);
    float q0 = g_dc[bn*3+0], q1 = g_dc[bn*3+1], q2 = g_dc[bn*3+2];
    float4 O0, O1, O2;
    #pragma unroll
    for (int c = 0; c < 4; c++){
        float o0,o1,o2;
        lna3((&P0.x)[c], (&P1.x)[c], (&P2.x)[c], q0, q1, q2, o0,o1,o2);
        (&O0.x)[c]=o0; (&O1.x)[c]=o1; (&O2.x)[c]=o2;
    }
    float* out = g_xcat256 + (size_t)bn*3*256 + oc;
    *(float4*)(out)       = O0;
    *(float4*)(out + 256) = O1;
    *(float4*)(out + 512) = O2;
}

// ------------------------- xm mean -------------------------------------------
__global__ void k_xm_part()
{
    int blk  = blockIdx.x;
    int slab = blk & 31;
    int bd3  = blk >> 5;
    int b = bd3 / 3, d = bd3 - b*3;
    int o = threadIdx.x;
    float s = 0.f;
    for (int nn = 0; nn < 64; nn++){
        int n = slab*64 + nn;
        s += g_xcat256[((size_t)(b*NPTS+n)*3 + d)*256 + o];
    }
    g_xmp[(size_t)(bd3*32 + slab)*128 + o] = s;
}

__global__ void k_xm_final()
{
    int t = blockIdx.x*blockDim.x + threadIdx.x;
    if (t >= BATCH*3*128) return;
    int bd3 = t >> 7, o = t & 127;
    float s = 0.f;
    for (int sl = 0; sl < 32; sl++) s += g_xmp[(size_t)(bd3*32+sl)*128 + o];
    g_xm[bd3*128 + o] = s * (1.f/2048.f);
}

__global__ void k_bias_i1(const float* __restrict__ wi1f, const float* __restrict__ wi1d)
{
    int t = blockIdx.x*blockDim.x + threadIdx.x;
    if (t >= BATCH*3*256) return;
    int bd3 = t >> 8, r = t & 255;
    const float* wrow = (r < 128) ? (wi1f + r*256) : (wi1d + (r-128)*256);
    float s = 0.f;
    for (int c = 0; c < 128; c++) s = fmaf(wrow[128+c], g_xm[bd3*128 + c], s);
    g_bias[bd3*256 + r] = s;
}

// ------------------------- i1 LNA (writes t128 only) ------------------------
__global__ void k_lna_pd()
{
    int t = blockIdx.x*blockDim.x + threadIdx.x;
    if (t >= BN_ALL*32) return;
    int bn = t >> 5, oc = (t & 31)*4;
    const float* Yb = g_Y + (size_t)bn*768 + oc;
    float4 P0 = *(const float4*)(Yb + 0*128);
    float4 P1 = *(const float4*)(Yb + 1*128);
    float4 P2 = *(const float4*)(Yb + 2*128);
    float4 Q0 = *(const float4*)(Yb + 3*128);
    float4 Q1 = *(const float4*)(Yb + 4*128);
    float4 Q2 = *(const float4*)(Yb + 5*128);
    float4 O0, O1, O2;
    #pragma unroll
    for (int c = 0; c < 4; c++){
        float o0,o1,o2;
        lna3((&P0.x)[c], (&P1.x)[c], (&P2.x)[c],
             (&Q0.x)[c], (&Q1.x)[c], (&Q2.x)[c], o0,o1,o2);
        (&O0.x)[c]=o0; (&O1.x)[c]=o1; (&O2.x)[c]=o2;
    }
    float* out = g_t128 + (size_t)bn*3*128 + oc;
    *(float4*)(out)=O0; *(float4*)(out+128)=O1; *(float4*)(out+256)=O2;
}

// ------------------------- final invariant (fused i2-LNA + dot) --------------
__global__ void __launch_bounds__(256) k_inv(float* __restrict__ out)
{
    __shared__ float tile[256*33];
    int n0 = blockIdx.x * 32;
    int b  = n0 / NPTS;
    int t  = threadIdx.x;
    int pg = t >> 6;             // 0..3 -> 8 points each
    int oc = (t & 63)*4;         // 4 o-channels
    bool hi = (oc >= 128);
    float4 a0c, a1c, a2c;
    if (hi){
        a0c = *(const float4*)&g_xm[(b*3+0)*128 + oc - 128];
        a1c = *(const float4*)&g_xm[(b*3+1)*128 + oc - 128];
        a2c = *(const float4*)&g_xm[(b*3+2)*128 + oc - 128];
    }
    for (int pp = 0; pp < 8; pp++){
        int p = pg*8 + pp;
        int bn = n0 + p;
        size_t base = (size_t)bn*3*256 + oc;
        float4 a0, a1, a2;
        if (hi){ a0 = a0c; a1 = a1c; a2 = a2c; }
        else {
            a0 = *(const float4*)&g_xcat256[base];
            a1 = *(const float4*)&g_xcat256[base + 256];
            a2 = *(const float4*)&g_xcat256[base + 512];
        }
        const float* Yb = g_Y + (size_t)bn*1536 + oc;
        float4 P0 = *(const float4*)(Yb + 0*256);
        float4 P1 = *(const float4*)(Yb + 1*256);
        float4 P2 = *(const float4*)(Yb + 2*256);
        float4 Q0 = *(const float4*)(Yb + 3*256);
        float4 Q1 = *(const float4*)(Yb + 4*256);
        float4 Q2 = *(const float4*)(Yb + 5*256);
        #pragma unroll
        for (int c = 0; c < 4; c++){
            float o0,o1,o2;
            lna3((&P0.x)[c], (&P1.x)[c], (&P2.x)[c],
                 (&Q0.x)[c], (&Q1.x)[c], (&Q2.x)[c], o0,o1,o2);
            float s = (&a0.x)[c]*o0 + (&a1.x)[c]*o1 + (&a2.x)[c]*o2;
            tile[(oc + c)*33 + p] = s;
        }
    }
    __syncthreads();
    int nn0 = n0 - b*NPTS;
    int p   = t & 31, og = t >> 5;
    for (int o = og; o < 256; o += 8)
        out[(size_t)(b*256 + o)*NPTS + nn0 + p] = tile[o*33 + p];
}

// ------------------------- launcher -----------------------------------------
extern "C" void kernel_launch(void* const* d_in, const int* in_sizes, int n_in,
                              void* d_out, int out_size)
{
    const float* x    = (const float*)d_in[0];
    const float* w1f  = (const float*)d_in[1];
    const float* w1d  = (const float*)d_in[2];
    const float* w2f  = (const float*)d_in[3];
    const float* w2d  = (const float*)d_in[4];
    const float* w3f  = (const float*)d_in[5];
    const float* w3d  = (const float*)d_in[6];
    const float* w4f  = (const float*)d_in[7];
    const float* w4d  = (const float*)d_in[8];
    const float* wcf  = (const float*)d_in[9];
    const float* wcd  = (const float*)d_in[10];
    const float* wi1f = (const float*)d_in[11];
    const float* wi1d = (const float*)d_in[12];
    const float* wi2f = (const float*)d_in[13];
    const float* wi2d = (const float*)d_in[14];
    float* out = (float*)d_out;

    cudaFuncSetAttribute(k_hgemm, cudaFuncAttributeMaxDynamicSharedMemorySize, HG_SMEM);

    // all weight prep in one launch, up front
    k_wcomb_all<<<(W_TOT+255)/256, 256>>>(w2f, w2d, w3f, w3d, w4f, w4d,
                                          wcf, wi1f, wi1d, wi2f, wi2d);

    k_prep<<<(BN_ALL+127)/128, 128>>>(x);
    k_knn_part<<<BN_ALL*4/128, 128>>>();
    k_knn_merge<<<(BN_ALL+127)/128, 128>>>();

    // ---- layer 1 (C=1 -> O=16)
    k_layer1<<<(BN_ALL*48+255)/256, 256>>>(w1f, w1d);
    k_gather<16,64><<<BN_ALL/64, 256>>>(0);

    // ---- layer 2 (C=16 -> O=32)
    k_hgemm<<<dim3(M_COLS/128, 1), 256, HG_SMEM>>>(0, 0, WOF_L2, 128, 16, 240, 0, 4, 32);
    k_gather<32,32><<<BN_ALL/32, 256>>>(16);

    // ---- layer 3 (C=32 -> O=64)
    k_hgemm<<<dim3(M_COLS/128, 2), 256, HG_SMEM>>>(0, 0, WOF_L3, 256, 32, 240, 16, 4, 64);
    k_gather<64,16><<<BN_ALL/16, 256>>>(48);

    // ---- layer 4 (C=64 -> O=128)
    k_hgemm<<<dim3(M_COLS/128, 4), 256, HG_SMEM>>>(0, 0, WOF_L4, 512, 64, 240, 48, 4, 128);
    k_gather<128,8><<<BN_ALL/8, 256>>>(112);

    // ---- concat layer (wcf 128x240, wcd 1x240)
    k_hgemm<<<dim3(M_COLS/128, 1), 256, HG_SMEM>>>(0, 0, WOF_C, 128, 240, 240, 0, 1, 128);
    k_dc<<<(M_COLS*32+255)/256, 256>>>(wcd);
    k_lna_c<<<(BN_ALL*32+255)/256, 256>>>();

    // ---- xm mean over N
    k_xm_part<<<BATCH*3*32, 128>>>();
    k_xm_final<<<(BATCH*3*128+255)/256, 256>>>();

    // ---- i1 (wi1f/wi1d 128x256; contract 128 + xm bias)
    k_bias_i1<<<(BATCH*3*256+255)/256, 256>>>(wi1f, wi1d);
    k_hgemm<<<dim3(M_COLS/128, 2), 256, HG_SMEM>>>(1, 1, WOF_I1, 256, 128, 256, 0, 2, 128);
    k_lna_pd<<<(BN_ALL*32+255)/256, 256>>>();

    // ---- i2 (wi2f/wi2d 256x128) -> LNA fused into k_inv
    k_hgemm<<<dim3(M_COLS/128, 4), 256, HG_SMEM>>>(2, 0, WOF_I2, 512, 128, 128, 0, 2, 256);

    // ---- invariant output (B,256,N)
    k_inv<<<BN_ALL/32, 256>>>(out);
}